// round 1
// baseline (speedup 1.0000x reference)
#include <cuda_runtime.h>
#include <math.h>

#define NN 100000
#define EE 1000000
#define IND 100
#define HH 4
#define DD 32
#define CC 47
#define HD 128
#define HC 188
#define EPSI 1e-5f
#define SLP 0.2f

// ---------------- scratch (static device memory; no allocation) ----------------
__device__ float g_fs[(size_t)NN * HC];
__device__ float g_fd[(size_t)NN * HC];
__device__ float g_res[(size_t)NN * HC];
__device__ float g_tmp[(size_t)NN * HC];
__device__ float g_h[(size_t)NN * HD];
__device__ float g_logits[(size_t)EE * HH];
__device__ int   g_rowptr[NN + 1];
__device__ float g_stats[2 * HD];

// ---------------- CSR row_ptr from sorted dst (binary search) ----------------
__global__ void rowptr_kernel(const int* __restrict__ dst, int* __restrict__ rowptr) {
    int n = blockIdx.x * blockDim.x + threadIdx.x;
    if (n > NN) return;
    int lo = 0, hi = EE;
    while (lo < hi) {
        int mid = (lo + hi) >> 1;
        if (dst[mid] < n) lo = mid + 1; else hi = mid;
    }
    rowptr[n] = lo;
}

// ---------------- tiled SGEMM with bias: C[M,Nc] = A[M,K] @ W[K,Nc] + b ----------------
#define BM 64
#define BN 64
#define BK 16
__global__ void gemm_bias(const float* __restrict__ A, const float* __restrict__ W,
                          const float* __restrict__ bias, float* __restrict__ C,
                          int M, int K, int Nc) {
    __shared__ float As[BK][BM + 1];
    __shared__ float Bs[BK][BN + 1];
    int bm = blockIdx.y * BM, bn = blockIdx.x * BN;
    int tid = threadIdx.x;            // 256 threads
    int tx = tid & 15, ty = tid >> 4; // 16x16
    float acc[4][4];
#pragma unroll
    for (int i = 0; i < 4; i++)
#pragma unroll
        for (int j = 0; j < 4; j++) acc[i][j] = 0.f;

    for (int k0 = 0; k0 < K; k0 += BK) {
#pragma unroll
        for (int i = 0; i < 4; i++) {
            int l = tid + i * 256;    // 0..1023
            int m = l >> 4, k = l & 15;
            int gm = bm + m, gk = k0 + k;
            As[k][m] = (gm < M && gk < K) ? A[(size_t)gm * K + gk] : 0.f;
        }
#pragma unroll
        for (int i = 0; i < 4; i++) {
            int l = tid + i * 256;
            int k = l >> 6, nn = l & 63;
            int gk = k0 + k, gn = bn + nn;
            Bs[k][nn] = (gk < K && gn < Nc) ? W[(size_t)gk * Nc + gn] : 0.f;
        }
        __syncthreads();
#pragma unroll
        for (int k = 0; k < BK; k++) {
            float a[4], b[4];
#pragma unroll
            for (int i = 0; i < 4; i++) a[i] = As[k][ty * 4 + i];
#pragma unroll
            for (int j = 0; j < 4; j++) b[j] = Bs[k][tx * 4 + j];
#pragma unroll
            for (int i = 0; i < 4; i++)
#pragma unroll
                for (int j = 0; j < 4; j++) acc[i][j] += a[i] * b[j];
        }
        __syncthreads();
    }
#pragma unroll
    for (int i = 0; i < 4; i++) {
        int gm = bm + ty * 4 + i;
        if (gm >= M) continue;
#pragma unroll
        for (int j = 0; j < 4; j++) {
            int gn = bn + tx * 4 + j;
            if (gn < Nc) C[(size_t)gm * Nc + gn] = acc[i][j] + bias[gn];
        }
    }
}

// ---------------- edge logits: warp per edge ----------------
__global__ void edge_logits(const float* __restrict__ fs, const float* __restrict__ fd,
                            const float* __restrict__ attn,
                            const int* __restrict__ src, const int* __restrict__ dst,
                            float* __restrict__ logits, int Dh) {
    int e = blockIdx.x * (blockDim.x >> 5) + (threadIdx.x >> 5);
    int lane = threadIdx.x & 31;
    if (e >= EE) return;
    int s = src[e], t = dst[e];
    int ld = HH * Dh;
    const float* fsr = fs + (size_t)s * ld;
    const float* fdr = fd + (size_t)t * ld;
#pragma unroll
    for (int h = 0; h < HH; h++) {
        float acc = 0.f;
        for (int d = lane; d < Dh; d += 32) {
            float v = fsr[h * Dh + d] + fdr[h * Dh + d];
            v = v > 0.f ? v : SLP * v;
            acc += v * attn[h * Dh + d];
        }
#pragma unroll
        for (int o = 16; o; o >>= 1) acc += __shfl_xor_sync(0xffffffffu, acc, o);
        if (lane == 0) logits[(size_t)e * HH + h] = acc;
    }
}

// ---------------- per-node softmax + aggregation (block per node, warp per head) ----------------
__global__ void node_agg(const float* __restrict__ fs, const float* __restrict__ logits,
                         const int* __restrict__ src, const int* __restrict__ rowptr,
                         const float* __restrict__ res, float* __restrict__ out,
                         int Dh, int do_relu) {
    int n = blockIdx.x;
    int w = threadIdx.x >> 5;   // head
    int lane = threadIdx.x & 31;
    int ld = HH * Dh;
    int e0 = rowptr[n], e1 = rowptr[n + 1];

    float m = -INFINITY;
    for (int e = e0; e < e1; e++) m = fmaxf(m, logits[(size_t)e * HH + w]);

    int d0 = lane, d1 = lane + 32;
    float acc0 = 0.f, acc1 = 0.f, ssum = 0.f;
    for (int e = e0; e < e1; e++) {
        float ex = __expf(logits[(size_t)e * HH + w] - m);
        ssum += ex;
        const float* frow = fs + (size_t)src[e] * ld + w * Dh;
        if (d0 < Dh) acc0 += ex * frow[d0];
        if (d1 < Dh) acc1 += ex * frow[d1];
    }
    float inv = (e1 > e0) ? 1.f / ssum : 0.f;
    size_t base = (size_t)n * ld + w * Dh;
    if (d0 < Dh) {
        float v = acc0 * inv + res[base + d0];
        if (do_relu) v = fmaxf(v, 0.f);
        out[base + d0] = v;
    }
    if (d1 < Dh) {
        float v = acc1 * inv + res[base + d1];
        if (do_relu) v = fmaxf(v, 0.f);
        out[base + d1] = v;
    }
}

// ---------------- BatchNorm (training-mode batch stats) ----------------
__global__ void zero_stats() {
    int i = threadIdx.x;
    if (i < 2 * HD) g_stats[i] = 0.f;
}

__global__ void bn_stats(const float* __restrict__ x) {
    int c = threadIdx.x;            // 128 threads = columns
    int per = (NN + gridDim.x - 1) / gridDim.x;
    int r0 = blockIdx.x * per;
    int r1 = min(NN, r0 + per);
    float s = 0.f, q = 0.f;
    for (int r = r0; r < r1; r++) {
        float v = x[(size_t)r * HD + c];
        s += v; q += v * v;
    }
    atomicAdd(&g_stats[c], s);
    atomicAdd(&g_stats[HD + c], q);
}

__global__ void bn_apply(const float* __restrict__ x, const float* __restrict__ g,
                         const float* __restrict__ b, float* __restrict__ out) {
    size_t i = (size_t)blockIdx.x * blockDim.x + threadIdx.x;
    if (i >= (size_t)NN * HD) return;
    int c = (int)(i & (HD - 1));
    float mu = g_stats[c] * (1.f / NN);
    float var = g_stats[HD + c] * (1.f / NN) - mu * mu;
    float v = g[c] * (x[i] - mu) * rsqrtf(var + EPSI) + b[c];
    out[i] = fmaxf(v, 0.f);
}

// ---------------- head mean + log_softmax (warp per node) ----------------
__global__ void final_logsoftmax(const float* __restrict__ h, float* __restrict__ out) {
    int n = blockIdx.x * (blockDim.x >> 5) + (threadIdx.x >> 5);
    int lane = threadIdx.x & 31;
    if (n >= NN) return;
    const float* row = h + (size_t)n * HC;
    int c0 = lane, c1 = lane + 32;
    bool a0 = c0 < CC, a1 = c1 < CC;
    float v0 = 0.f, v1 = 0.f;
    if (a0) v0 = 0.25f * (row[c0] + row[CC + c0] + row[2 * CC + c0] + row[3 * CC + c0]);
    if (a1) v1 = 0.25f * (row[c1] + row[CC + c1] + row[2 * CC + c1] + row[3 * CC + c1]);
    float mx = fmaxf(a0 ? v0 : -INFINITY, a1 ? v1 : -INFINITY);
#pragma unroll
    for (int o = 16; o; o >>= 1) mx = fmaxf(mx, __shfl_xor_sync(0xffffffffu, mx, o));
    float s = (a0 ? __expf(v0 - mx) : 0.f) + (a1 ? __expf(v1 - mx) : 0.f);
#pragma unroll
    for (int o = 16; o; o >>= 1) s += __shfl_xor_sync(0xffffffffu, s, o);
    float ls = logf(s);
    if (a0) out[(size_t)n * CC + c0] = v0 - mx - ls;
    if (a1) out[(size_t)n * CC + c1] = v1 - mx - ls;
}

// ---------------- launch ----------------
static inline dim3 gemm_grid(int M, int Nc) {
    return dim3((Nc + BN - 1) / BN, (M + BM - 1) / BM);
}

extern "C" void kernel_launch(void* const* d_in, const int* in_sizes, int n_in,
                              void* d_out, int out_size) {
    const float* x     = (const float*)d_in[0];
    const int*   src   = (const int*)d_in[1];
    const int*   dst   = (const int*)d_in[2];
    const float* Wsrc0 = (const float*)d_in[3];
    const float* bsrc0 = (const float*)d_in[4];
    const float* Wdst0 = (const float*)d_in[5];
    const float* bdst0 = (const float*)d_in[6];
    const float* attn0 = (const float*)d_in[7];
    const float* Wres0 = (const float*)d_in[8];
    const float* bres0 = (const float*)d_in[9];
    const float* Wsrc1 = (const float*)d_in[10];
    const float* bsrc1 = (const float*)d_in[11];
    const float* Wdst1 = (const float*)d_in[12];
    const float* bdst1 = (const float*)d_in[13];
    const float* attn1 = (const float*)d_in[14];
    const float* Wsrc2 = (const float*)d_in[15];
    const float* bsrc2 = (const float*)d_in[16];
    const float* Wdst2 = (const float*)d_in[17];
    const float* bdst2 = (const float*)d_in[18];
    const float* attn2 = (const float*)d_in[19];
    const float* Wres2 = (const float*)d_in[20];
    const float* bres2 = (const float*)d_in[21];
    const float* g0    = (const float*)d_in[22];
    const float* be0   = (const float*)d_in[23];
    const float* g1    = (const float*)d_in[24];
    const float* be1   = (const float*)d_in[25];
    float* out = (float*)d_out;

    float *fs, *fd, *res, *tmp, *h, *logits;
    int* rowptr;
    cudaGetSymbolAddress((void**)&fs, g_fs);
    cudaGetSymbolAddress((void**)&fd, g_fd);
    cudaGetSymbolAddress((void**)&res, g_res);
    cudaGetSymbolAddress((void**)&tmp, g_tmp);
    cudaGetSymbolAddress((void**)&h, g_h);
    cudaGetSymbolAddress((void**)&logits, g_logits);
    cudaGetSymbolAddress((void**)&rowptr, g_rowptr);

    rowptr_kernel<<<(NN + 1 + 255) / 256, 256>>>(dst, rowptr);

    const int edge_grid = (EE + 7) / 8;           // 8 warps / block
    const int bn_elems_grid = (int)(((size_t)NN * HD + 255) / 256);

    // ---- layer 0: x[100k,100] -> 128, Linear residual ----
    gemm_bias<<<gemm_grid(NN, HD), 256>>>(x, Wsrc0, bsrc0, fs, NN, IND, HD);
    gemm_bias<<<gemm_grid(NN, HD), 256>>>(x, Wdst0, bdst0, fd, NN, IND, HD);
    gemm_bias<<<gemm_grid(NN, HD), 256>>>(x, Wres0, bres0, res, NN, IND, HD);
    edge_logits<<<edge_grid, 256>>>(fs, fd, attn0, src, dst, logits, DD);
    node_agg<<<NN, 128>>>(fs, logits, src, rowptr, res, tmp, DD, 1);
    zero_stats<<<1, 256>>>();
    bn_stats<<<2048, 128>>>(tmp);
    bn_apply<<<bn_elems_grid, 256>>>(tmp, g0, be0, h);

    // ---- layer 1: 128 -> 128, Identity residual ----
    gemm_bias<<<gemm_grid(NN, HD), 256>>>(h, Wsrc1, bsrc1, fs, NN, HD, HD);
    gemm_bias<<<gemm_grid(NN, HD), 256>>>(h, Wdst1, bdst1, fd, NN, HD, HD);
    edge_logits<<<edge_grid, 256>>>(fs, fd, attn1, src, dst, logits, DD);
    node_agg<<<NN, 128>>>(fs, logits, src, rowptr, h, tmp, DD, 1);
    zero_stats<<<1, 256>>>();
    bn_stats<<<2048, 128>>>(tmp);
    bn_apply<<<bn_elems_grid, 256>>>(tmp, g1, be1, h);

    // ---- layer 2: 128 -> 188, Linear residual, no BN ----
    gemm_bias<<<gemm_grid(NN, HC), 256>>>(h, Wsrc2, bsrc2, fs, NN, HD, HC);
    gemm_bias<<<gemm_grid(NN, HC), 256>>>(h, Wdst2, bdst2, fd, NN, HD, HC);
    gemm_bias<<<gemm_grid(NN, HC), 256>>>(h, Wres2, bres2, res, NN, HD, HC);
    edge_logits<<<edge_grid, 256>>>(fs, fd, attn2, src, dst, logits, CC);
    node_agg<<<NN, 128>>>(fs, logits, src, rowptr, res, tmp, CC, 0);

    final_logsoftmax<<<(NN + 7) / 8, 256>>>(tmp, out);
}

// round 2
// speedup vs baseline: 1.6919x; 1.6919x over previous
#include <cuda_runtime.h>
#include <math.h>

#define NN 100000
#define EE 1000000
#define IND 100
#define HH 4
#define DD 32
#define CC 47
#define HD 128
#define HC 188
#define EPSI 1e-5f
#define SLP 0.2f

// ---------------- scratch (static device memory; no allocation) ----------------
__device__ float g_fs[(size_t)NN * HC];
__device__ float g_fd[(size_t)NN * HC];
__device__ float g_res[(size_t)NN * HC];
__device__ float g_tmp[(size_t)NN * HC];
__device__ float g_h[(size_t)NN * HD];
__device__ float g_logits[(size_t)EE * HH];
__device__ int   g_rowptr[NN + 1];
__device__ float g_stats[2 * HD];

// ---------------- CSR row_ptr from sorted dst (binary search) ----------------
__global__ void rowptr_kernel(const int* __restrict__ dst, int* __restrict__ rowptr) {
    int n = blockIdx.x * blockDim.x + threadIdx.x;
    if (n > NN) return;
    int lo = 0, hi = EE;
    while (lo < hi) {
        int mid = (lo + hi) >> 1;
        if (dst[mid] < n) lo = mid + 1; else hi = mid;
    }
    rowptr[n] = lo;
}

// ---------------- SGEMM 128x64 tile, 8x4 micro-tile, float4 everywhere ----------------
#define BM 128
#define BN 64
#define BK 16
__global__ __launch_bounds__(256) void gemm_bias(
    const float* __restrict__ A, const float* __restrict__ W,
    const float* __restrict__ bias, float* __restrict__ C,
    int M, int K, int Nc) {
    __shared__ float As[BK][BM + 4];
    __shared__ float Bs[BK][BN + 4];
    int bm = blockIdx.y * BM, bn = blockIdx.x * BN;
    int tid = threadIdx.x;
    int tx = tid & 15, ty = tid >> 4;       // 16x16 thread grid

    float acc[8][4];
#pragma unroll
    for (int i = 0; i < 8; i++)
#pragma unroll
        for (int j = 0; j < 4; j++) acc[i][j] = 0.f;

    const float4* A4 = (const float4*)A;
    const float4* W4 = (const float4*)W;
    int K4 = K >> 2, Nc4 = Nc >> 2;

    for (int k0 = 0; k0 < K; k0 += BK) {
        // load A tile: 128 rows x 16 k = 512 float4, 2 per thread
#pragma unroll
        for (int i = 0; i < 2; i++) {
            int idx = tid + i * 256;
            int m = idx >> 2, kq = idx & 3;
            int gm = bm + m, gk = k0 + kq * 4;
            float4 a = make_float4(0.f, 0.f, 0.f, 0.f);
            if (gm < M && gk < K) a = A4[(size_t)gm * K4 + (gk >> 2)];
            As[kq * 4 + 0][m] = a.x;
            As[kq * 4 + 1][m] = a.y;
            As[kq * 4 + 2][m] = a.z;
            As[kq * 4 + 3][m] = a.w;
        }
        // load B tile: 16 k x 64 n = 256 float4, 1 per thread
        {
            int k = tid >> 4, nq = tid & 15;
            int gk = k0 + k, gn = bn + nq * 4;
            float4 b = make_float4(0.f, 0.f, 0.f, 0.f);
            if (gk < K && gn < Nc) b = W4[(size_t)gk * Nc4 + (gn >> 2)];
            *(float4*)&Bs[k][nq * 4] = b;
        }
        __syncthreads();
#pragma unroll
        for (int k = 0; k < BK; k++) {
            float4 a0 = *(const float4*)&As[k][ty * 8];
            float4 a1 = *(const float4*)&As[k][ty * 8 + 4];
            float4 b  = *(const float4*)&Bs[k][tx * 4];
            float av[8] = {a0.x, a0.y, a0.z, a0.w, a1.x, a1.y, a1.z, a1.w};
            float bv[4] = {b.x, b.y, b.z, b.w};
#pragma unroll
            for (int i = 0; i < 8; i++)
#pragma unroll
                for (int j = 0; j < 4; j++) acc[i][j] += av[i] * bv[j];
        }
        __syncthreads();
    }
    // epilogue
    int gn = bn + tx * 4;
    if (gn < Nc) {
        float4 bb = *(const float4*)&bias[gn];
#pragma unroll
        for (int i = 0; i < 8; i++) {
            int gm = bm + ty * 8 + i;
            if (gm >= M) break;
            float4 o = make_float4(acc[i][0] + bb.x, acc[i][1] + bb.y,
                                   acc[i][2] + bb.z, acc[i][3] + bb.w);
            *(float4*)&C[(size_t)gm * Nc + gn] = o;
        }
    }
}

// ---------------- edge logits, Dh=32: warp per edge, all heads at once ----------------
__global__ void edge_logits32(const float4* __restrict__ fs, const float4* __restrict__ fd,
                              const float4* __restrict__ attn,
                              const int* __restrict__ src, const int* __restrict__ dst,
                              float* __restrict__ logits) {
    int e = blockIdx.x * (blockDim.x >> 5) + (threadIdx.x >> 5);
    if (e >= EE) return;
    int lane = threadIdx.x & 31;
    int h = lane >> 3, q = lane & 7;      // lane covers head h, float4 q (d = q*4..q*4+3)
    int s = src[e], t = dst[e];
    float4 a = fs[(size_t)s * 32 + h * 8 + q];
    float4 b = fd[(size_t)t * 32 + h * 8 + q];
    float4 w = attn[h * 8 + q];
    float vx = a.x + b.x; vx = vx > 0.f ? vx : SLP * vx;
    float vy = a.y + b.y; vy = vy > 0.f ? vy : SLP * vy;
    float vz = a.z + b.z; vz = vz > 0.f ? vz : SLP * vz;
    float vw = a.w + b.w; vw = vw > 0.f ? vw : SLP * vw;
    float acc = vx * w.x + vy * w.y + vz * w.z + vw * w.w;
    acc += __shfl_xor_sync(0xffffffffu, acc, 4);
    acc += __shfl_xor_sync(0xffffffffu, acc, 2);
    acc += __shfl_xor_sync(0xffffffffu, acc, 1);
    if (q == 0) logits[(size_t)e * HH + h] = acc;
}

// ---------------- edge logits, generic Dh (layer 2, Dh=47) ----------------
__global__ void edge_logitsN(const float* __restrict__ fs, const float* __restrict__ fd,
                             const float* __restrict__ attn,
                             const int* __restrict__ src, const int* __restrict__ dst,
                             float* __restrict__ logits, int Dh) {
    int e = blockIdx.x * (blockDim.x >> 5) + (threadIdx.x >> 5);
    if (e >= EE) return;
    int lane = threadIdx.x & 31;
    int h = lane >> 3, j = lane & 7;
    int s = src[e], t = dst[e];
    int ld = HH * Dh;
    const float* fsr = fs + (size_t)s * ld + h * Dh;
    const float* fdr = fd + (size_t)t * ld + h * Dh;
    const float* at = attn + h * Dh;
    float acc = 0.f;
    for (int d = j; d < Dh; d += 8) {
        float v = fsr[d] + fdr[d];
        v = v > 0.f ? v : SLP * v;
        acc += v * at[d];
    }
    acc += __shfl_xor_sync(0xffffffffu, acc, 4);
    acc += __shfl_xor_sync(0xffffffffu, acc, 2);
    acc += __shfl_xor_sync(0xffffffffu, acc, 1);
    if (j == 0) logits[(size_t)e * HH + h] = acc;
}

// ---------------- node softmax + aggregation: warp per (node, head) ----------------
__global__ void node_agg(const float* __restrict__ fs, const float* __restrict__ logits,
                         const int* __restrict__ src, const int* __restrict__ rowptr,
                         const float* __restrict__ res, float* __restrict__ out,
                         int Dh, int do_relu) {
    int gw = blockIdx.x * (blockDim.x >> 5) + (threadIdx.x >> 5);
    if (gw >= NN * HH) return;
    int n = gw >> 2, h = gw & 3;
    int lane = threadIdx.x & 31;
    int ld = HH * Dh;
    int e0 = rowptr[n], e1 = rowptr[n + 1];

    // lane-parallel max
    float m = -INFINITY;
    for (int e = e0 + lane; e < e1; e += 32) m = fmaxf(m, logits[(size_t)e * HH + h]);
#pragma unroll
    for (int o = 16; o; o >>= 1) m = fmaxf(m, __shfl_xor_sync(0xffffffffu, m, o));

    int d0 = lane, d1 = lane + 32;
    bool b0 = d0 < Dh, b1 = d1 < Dh;
    float acc0 = 0.f, acc1 = 0.f, ssum = 0.f;
    int e = e0;
    for (; e + 1 < e1; e += 2) {
        float l0 = logits[(size_t)e * HH + h];
        float l1 = logits[(size_t)(e + 1) * HH + h];
        int s0 = src[e], s1 = src[e + 1];
        const float* r0 = fs + (size_t)s0 * ld + h * Dh;
        const float* r1 = fs + (size_t)s1 * ld + h * Dh;
        float f00 = b0 ? r0[d0] : 0.f;
        float f01 = b1 ? r0[d1] : 0.f;
        float f10 = b0 ? r1[d0] : 0.f;
        float f11 = b1 ? r1[d1] : 0.f;
        float ex0 = __expf(l0 - m), ex1 = __expf(l1 - m);
        ssum += ex0 + ex1;
        acc0 += ex0 * f00 + ex1 * f10;
        acc1 += ex0 * f01 + ex1 * f11;
    }
    if (e < e1) {
        float l0 = logits[(size_t)e * HH + h];
        int s0 = src[e];
        const float* r0 = fs + (size_t)s0 * ld + h * Dh;
        float ex0 = __expf(l0 - m);
        ssum += ex0;
        if (b0) acc0 += ex0 * r0[d0];
        if (b1) acc1 += ex0 * r0[d1];
    }
    float inv = (e1 > e0) ? 1.f / ssum : 0.f;
    size_t base = (size_t)n * ld + h * Dh;
    if (b0) {
        float v = acc0 * inv + res[base + d0];
        if (do_relu) v = fmaxf(v, 0.f);
        out[base + d0] = v;
    }
    if (b1) {
        float v = acc1 * inv + res[base + d1];
        if (do_relu) v = fmaxf(v, 0.f);
        out[base + d1] = v;
    }
}

// ---------------- BatchNorm (training-mode batch stats) ----------------
__global__ void zero_stats() {
    int i = threadIdx.x;
    if (i < 2 * HD) g_stats[i] = 0.f;
}

__global__ void bn_stats(const float* __restrict__ x) {
    int c = threadIdx.x;            // 128 threads = columns
    int per = (NN + gridDim.x - 1) / gridDim.x;
    int r0 = blockIdx.x * per;
    int r1 = min(NN, r0 + per);
    float s = 0.f, q = 0.f;
    for (int r = r0; r < r1; r++) {
        float v = x[(size_t)r * HD + c];
        s += v; q += v * v;
    }
    atomicAdd(&g_stats[c], s);
    atomicAdd(&g_stats[HD + c], q);
}

__global__ void bn_apply(const float* __restrict__ x, const float* __restrict__ g,
                         const float* __restrict__ b, float* __restrict__ out) {
    size_t i = (size_t)blockIdx.x * blockDim.x + threadIdx.x;
    if (i >= (size_t)NN * HD) return;
    int c = (int)(i & (HD - 1));
    float mu = g_stats[c] * (1.f / NN);
    float var = g_stats[HD + c] * (1.f / NN) - mu * mu;
    float v = g[c] * (x[i] - mu) * rsqrtf(var + EPSI) + b[c];
    out[i] = fmaxf(v, 0.f);
}

// ---------------- head mean + log_softmax (warp per node) ----------------
__global__ void final_logsoftmax(const float* __restrict__ h, float* __restrict__ out) {
    int n = blockIdx.x * (blockDim.x >> 5) + (threadIdx.x >> 5);
    int lane = threadIdx.x & 31;
    if (n >= NN) return;
    const float* row = h + (size_t)n * HC;
    int c0 = lane, c1 = lane + 32;
    bool a0 = c0 < CC, a1 = c1 < CC;
    float v0 = 0.f, v1 = 0.f;
    if (a0) v0 = 0.25f * (row[c0] + row[CC + c0] + row[2 * CC + c0] + row[3 * CC + c0]);
    if (a1) v1 = 0.25f * (row[c1] + row[CC + c1] + row[2 * CC + c1] + row[3 * CC + c1]);
    float mx = fmaxf(a0 ? v0 : -INFINITY, a1 ? v1 : -INFINITY);
#pragma unroll
    for (int o = 16; o; o >>= 1) mx = fmaxf(mx, __shfl_xor_sync(0xffffffffu, mx, o));
    float s = (a0 ? __expf(v0 - mx) : 0.f) + (a1 ? __expf(v1 - mx) : 0.f);
#pragma unroll
    for (int o = 16; o; o >>= 1) s += __shfl_xor_sync(0xffffffffu, s, o);
    float ls = logf(s);
    if (a0) out[(size_t)n * CC + c0] = v0 - mx - ls;
    if (a1) out[(size_t)n * CC + c1] = v1 - mx - ls;
}

// ---------------- launch ----------------
static inline dim3 gemm_grid(int M, int Nc) {
    return dim3((Nc + BN - 1) / BN, (M + BM - 1) / BM);
}

extern "C" void kernel_launch(void* const* d_in, const int* in_sizes, int n_in,
                              void* d_out, int out_size) {
    const float* x     = (const float*)d_in[0];
    const int*   src   = (const int*)d_in[1];
    const int*   dst   = (const int*)d_in[2];
    const float* Wsrc0 = (const float*)d_in[3];
    const float* bsrc0 = (const float*)d_in[4];
    const float* Wdst0 = (const float*)d_in[5];
    const float* bdst0 = (const float*)d_in[6];
    const float* attn0 = (const float*)d_in[7];
    const float* Wres0 = (const float*)d_in[8];
    const float* bres0 = (const float*)d_in[9];
    const float* Wsrc1 = (const float*)d_in[10];
    const float* bsrc1 = (const float*)d_in[11];
    const float* Wdst1 = (const float*)d_in[12];
    const float* bdst1 = (const float*)d_in[13];
    const float* attn1 = (const float*)d_in[14];
    const float* Wsrc2 = (const float*)d_in[15];
    const float* bsrc2 = (const float*)d_in[16];
    const float* Wdst2 = (const float*)d_in[17];
    const float* bdst2 = (const float*)d_in[18];
    const float* attn2 = (const float*)d_in[19];
    const float* Wres2 = (const float*)d_in[20];
    const float* bres2 = (const float*)d_in[21];
    const float* g0    = (const float*)d_in[22];
    const float* be0   = (const float*)d_in[23];
    const float* g1    = (const float*)d_in[24];
    const float* be1   = (const float*)d_in[25];
    float* out = (float*)d_out;

    float *fs, *fd, *res, *tmp, *h, *logits;
    int* rowptr;
    cudaGetSymbolAddress((void**)&fs, g_fs);
    cudaGetSymbolAddress((void**)&fd, g_fd);
    cudaGetSymbolAddress((void**)&res, g_res);
    cudaGetSymbolAddress((void**)&tmp, g_tmp);
    cudaGetSymbolAddress((void**)&h, g_h);
    cudaGetSymbolAddress((void**)&logits, g_logits);
    cudaGetSymbolAddress((void**)&rowptr, g_rowptr);

    rowptr_kernel<<<(NN + 1 + 255) / 256, 256>>>(dst, rowptr);

    const int edge_grid = (EE + 7) / 8;                       // 8 warps/block, warp/edge
    const int node_grid = (NN * HH + 7) / 8;                  // warp/(node,head)
    const int bn_elems_grid = (int)(((size_t)NN * HD + 255) / 256);

    // ---- layer 0: x[100k,100] -> 128, Linear residual ----
    gemm_bias<<<gemm_grid(NN, HD), 256>>>(x, Wsrc0, bsrc0, fs, NN, IND, HD);
    gemm_bias<<<gemm_grid(NN, HD), 256>>>(x, Wdst0, bdst0, fd, NN, IND, HD);
    gemm_bias<<<gemm_grid(NN, HD), 256>>>(x, Wres0, bres0, res, NN, IND, HD);
    edge_logits32<<<edge_grid, 256>>>((const float4*)fs, (const float4*)fd,
                                      (const float4*)attn0, src, dst, logits);
    node_agg<<<node_grid, 256>>>(fs, logits, src, rowptr, res, tmp, DD, 1);
    zero_stats<<<1, 256>>>();
    bn_stats<<<2048, 128>>>(tmp);
    bn_apply<<<bn_elems_grid, 256>>>(tmp, g0, be0, h);

    // ---- layer 1: 128 -> 128, Identity residual ----
    gemm_bias<<<gemm_grid(NN, HD), 256>>>(h, Wsrc1, bsrc1, fs, NN, HD, HD);
    gemm_bias<<<gemm_grid(NN, HD), 256>>>(h, Wdst1, bdst1, fd, NN, HD, HD);
    edge_logits32<<<edge_grid, 256>>>((const float4*)fs, (const float4*)fd,
                                      (const float4*)attn1, src, dst, logits);
    node_agg<<<node_grid, 256>>>(fs, logits, src, rowptr, h, tmp, DD, 1);
    zero_stats<<<1, 256>>>();
    bn_stats<<<2048, 128>>>(tmp);
    bn_apply<<<bn_elems_grid, 256>>>(tmp, g1, be1, h);

    // ---- layer 2: 128 -> 188, Linear residual, no BN ----
    gemm_bias<<<gemm_grid(NN, HC), 256>>>(h, Wsrc2, bsrc2, fs, NN, HD, HC);
    gemm_bias<<<gemm_grid(NN, HC), 256>>>(h, Wdst2, bdst2, fd, NN, HD, HC);
    gemm_bias<<<gemm_grid(NN, HC), 256>>>(h, Wres2, bres2, res, NN, HD, HC);
    edge_logitsN<<<edge_grid, 256>>>(fs, fd, attn2, src, dst, logits, CC);
    node_agg<<<node_grid, 256>>>(fs, logits, src, rowptr, res, tmp, CC, 0);

    final_logsoftmax<<<(NN + 7) / 8, 256>>>(tmp, out);
}

// round 3
// speedup vs baseline: 1.9876x; 1.1747x over previous
#include <cuda_runtime.h>
#include <math.h>

#define NN 100000
#define EE 1000000
#define IND 100
#define HH 4
#define DD 32
#define CC 47
#define HD 128
#define HC 188
#define EPSI 1e-5f
#define SLP 0.2f

// ---------------- scratch (static device memory; no allocation) ----------------
__device__ float g_fs[(size_t)NN * HC];
__device__ float g_fd[(size_t)NN * HC];
__device__ float g_res[(size_t)NN * HC];
__device__ float g_tmp[(size_t)NN * HC];
__device__ float g_h[(size_t)NN * HD];
__device__ int   g_rowptr[NN + 1];
__device__ float g_stats[2 * HD];

// ---------------- CSR row_ptr from sorted dst (binary search) ----------------
__global__ void rowptr_kernel(const int* __restrict__ dst, int* __restrict__ rowptr) {
    int n = blockIdx.x * blockDim.x + threadIdx.x;
    if (n > NN) return;
    int lo = 0, hi = EE;
    while (lo < hi) {
        int mid = (lo + hi) >> 1;
        if (dst[mid] < n) lo = mid + 1; else hi = mid;
    }
    rowptr[n] = lo;
}

// ---------------- SGEMM: 128x128 tile, 8x8 micro-tile, double-buffered ----------------
// Packs up to 3 outputs (same A, different W/bias/C) into one launch:
//   which = blockIdx.x / tilesPer selects (W,bias,C); col tile = blockIdx.x % tilesPer.
#define BM 128
#define BN 128
#define BK 16

__global__ __launch_bounds__(256) void gemm_bias3(
    const float* __restrict__ A,
    const float* __restrict__ W0, const float* __restrict__ W1, const float* __restrict__ W2,
    const float* __restrict__ b0p, const float* __restrict__ b1p, const float* __restrict__ b2p,
    float* __restrict__ C0, float* __restrict__ C1, float* __restrict__ C2,
    int M, int K, int Nc, int tilesPer) {
    __shared__ float As[2][BK][BM + 4];
    __shared__ float Bs[2][BK][BN + 8];

    int which = blockIdx.x / tilesPer;
    int xt = blockIdx.x - which * tilesPer;
    const float* W = which == 0 ? W0 : (which == 1 ? W1 : W2);
    const float* bias = which == 0 ? b0p : (which == 1 ? b1p : b2p);
    float* C = which == 0 ? C0 : (which == 1 ? C1 : C2);

    int bm = blockIdx.y * BM, bn = xt * BN;
    int tid = threadIdx.x;
    int tx = tid & 15, ty = tid >> 4;

    float acc[8][8];
#pragma unroll
    for (int i = 0; i < 8; i++)
#pragma unroll
        for (int j = 0; j < 8; j++) acc[i][j] = 0.f;

    const float4* A4 = (const float4*)A;
    const float4* W4 = (const float4*)W;
    int K4 = K >> 2, Nc4 = Nc >> 2;
    int T = (K + BK - 1) / BK;

    float4 rA[2], rB[2];

    // prologue: load tile 0
#pragma unroll
    for (int i = 0; i < 2; i++) {
        int idx = tid + i * 256;
        int m = idx >> 2, kq = idx & 3;
        int gm = bm + m, gk = kq * 4;
        rA[i] = make_float4(0.f, 0.f, 0.f, 0.f);
        if (gm < M && gk < K) rA[i] = A4[(size_t)gm * K4 + (gk >> 2)];
    }
#pragma unroll
    for (int i = 0; i < 2; i++) {
        int idx = tid + i * 256;
        int k = idx >> 5, nq = idx & 31;
        int gk = k, gn = bn + nq * 4;
        rB[i] = make_float4(0.f, 0.f, 0.f, 0.f);
        if (gk < K && gn < Nc) rB[i] = W4[(size_t)gk * Nc4 + (gn >> 2)];
    }
#pragma unroll
    for (int i = 0; i < 2; i++) {
        int idx = tid + i * 256;
        int m = idx >> 2, kq = idx & 3;
        As[0][kq * 4 + 0][m] = rA[i].x;
        As[0][kq * 4 + 1][m] = rA[i].y;
        As[0][kq * 4 + 2][m] = rA[i].z;
        As[0][kq * 4 + 3][m] = rA[i].w;
    }
#pragma unroll
    for (int i = 0; i < 2; i++) {
        int idx = tid + i * 256;
        int k = idx >> 5, nq = idx & 31;
        *(float4*)&Bs[0][k][nq * 4] = rB[i];
    }
    __syncthreads();

    for (int t = 0; t < T; t++) {
        int cur = t & 1;
        if (t + 1 < T) {
            int k0 = (t + 1) * BK;
#pragma unroll
            for (int i = 0; i < 2; i++) {
                int idx = tid + i * 256;
                int m = idx >> 2, kq = idx & 3;
                int gm = bm + m, gk = k0 + kq * 4;
                rA[i] = make_float4(0.f, 0.f, 0.f, 0.f);
                if (gm < M && gk < K) rA[i] = A4[(size_t)gm * K4 + (gk >> 2)];
            }
#pragma unroll
            for (int i = 0; i < 2; i++) {
                int idx = tid + i * 256;
                int k = idx >> 5, nq = idx & 31;
                int gk = k0 + k, gn = bn + nq * 4;
                rB[i] = make_float4(0.f, 0.f, 0.f, 0.f);
                if (gk < K && gn < Nc) rB[i] = W4[(size_t)gk * Nc4 + (gn >> 2)];
            }
        }
#pragma unroll
        for (int k = 0; k < BK; k++) {
            float4 a0 = *(const float4*)&As[cur][k][ty * 8];
            float4 a1 = *(const float4*)&As[cur][k][ty * 8 + 4];
            float4 c0 = *(const float4*)&Bs[cur][k][tx * 8];
            float4 c1 = *(const float4*)&Bs[cur][k][tx * 8 + 4];
            float av[8] = {a0.x, a0.y, a0.z, a0.w, a1.x, a1.y, a1.z, a1.w};
            float bv[8] = {c0.x, c0.y, c0.z, c0.w, c1.x, c1.y, c1.z, c1.w};
#pragma unroll
            for (int i = 0; i < 8; i++)
#pragma unroll
                for (int j = 0; j < 8; j++) acc[i][j] += av[i] * bv[j];
        }
        if (t + 1 < T) {
            int nxt = (t + 1) & 1;
#pragma unroll
            for (int i = 0; i < 2; i++) {
                int idx = tid + i * 256;
                int m = idx >> 2, kq = idx & 3;
                As[nxt][kq * 4 + 0][m] = rA[i].x;
                As[nxt][kq * 4 + 1][m] = rA[i].y;
                As[nxt][kq * 4 + 2][m] = rA[i].z;
                As[nxt][kq * 4 + 3][m] = rA[i].w;
            }
#pragma unroll
            for (int i = 0; i < 2; i++) {
                int idx = tid + i * 256;
                int k = idx >> 5, nq = idx & 31;
                *(float4*)&Bs[nxt][k][nq * 4] = rB[i];
            }
        }
        __syncthreads();
    }

    // epilogue
    int gn0 = bn + tx * 8;
    int gn1 = gn0 + 4;
    bool cok0 = gn0 + 4 <= Nc, cok1 = gn1 + 4 <= Nc;
    float4 bb0 = make_float4(0.f, 0.f, 0.f, 0.f), bb1 = bb0;
    if (cok0) bb0 = *(const float4*)&bias[gn0];
    if (cok1) bb1 = *(const float4*)&bias[gn1];
#pragma unroll
    for (int i = 0; i < 8; i++) {
        int gm = bm + ty * 8 + i;
        if (gm >= M) break;
        if (cok0) {
            float4 o = make_float4(acc[i][0] + bb0.x, acc[i][1] + bb0.y,
                                   acc[i][2] + bb0.z, acc[i][3] + bb0.w);
            *(float4*)&C[(size_t)gm * Nc + gn0] = o;
        }
        if (cok1) {
            float4 o = make_float4(acc[i][4] + bb1.x, acc[i][5] + bb1.y,
                                   acc[i][6] + bb1.z, acc[i][7] + bb1.w);
            *(float4*)&C[(size_t)gm * Nc + gn1] = o;
        }
    }
}

// ---------------- fused GATv2 message pass: warp per (node, head), online softmax ----------------
template <int DH, bool RELU>
__global__ void gat_fused(const float* __restrict__ fs, const float* __restrict__ fd,
                          const float* __restrict__ attn,
                          const int* __restrict__ src, const int* __restrict__ rowptr,
                          const float* __restrict__ res, float* __restrict__ out) {
    const int LD = HH * DH;
    int gw = blockIdx.x * (blockDim.x >> 5) + (threadIdx.x >> 5);
    if (gw >= NN * HH) return;
    int n = gw >> 2, h = gw & 3;
    int lane = threadIdx.x & 31;
    int d0 = lane, d1 = lane + 32;
    const bool b1 = (DH > 32) && (d1 < DH);

    size_t nb = (size_t)n * LD + h * DH;
    float fd0 = fd[nb + d0 < nb + DH ? nb + d0 : nb];   // d0 < 32 <= DH always
    fd0 = fd[nb + d0];
    float a0 = attn[h * DH + d0];
    float fd1 = b1 ? fd[nb + d1] : 0.f;
    float a1 = b1 ? attn[h * DH + d1] : 0.f;

    int e0 = rowptr[n], e1 = rowptr[n + 1];

    float m = -INFINITY, ssum = 0.f, acc0 = 0.f, acc1 = 0.f;
    int e = e0;
    for (; e + 1 < e1; e += 2) {
        int s0 = src[e], s1 = src[e + 1];
        const float* r0 = fs + (size_t)s0 * LD + h * DH;
        const float* r1 = fs + (size_t)s1 * LD + h * DH;
        float f00 = r0[d0];
        float f10 = r1[d0];
        float f01 = b1 ? r0[d1] : 0.f;
        float f11 = b1 ? r1[d1] : 0.f;
        float u0 = f00 + fd0; u0 = u0 > 0.f ? u0 : SLP * u0;
        float w0 = f01 + fd1; w0 = w0 > 0.f ? w0 : SLP * w0;
        float u1 = f10 + fd0; u1 = u1 > 0.f ? u1 : SLP * u1;
        float w1 = f11 + fd1; w1 = w1 > 0.f ? w1 : SLP * w1;
        float l0 = u0 * a0 + w0 * a1;
        float l1 = u1 * a0 + w1 * a1;
#pragma unroll
        for (int o = 16; o; o >>= 1) {
            l0 += __shfl_xor_sync(0xffffffffu, l0, o);
            l1 += __shfl_xor_sync(0xffffffffu, l1, o);
        }
        float nm = fmaxf(m, fmaxf(l0, l1));
        float sc = __expf(m - nm);
        float w0e = __expf(l0 - nm);
        float w1e = __expf(l1 - nm);
        ssum = ssum * sc + w0e + w1e;
        acc0 = acc0 * sc + w0e * f00 + w1e * f10;
        acc1 = acc1 * sc + w0e * f01 + w1e * f11;
        m = nm;
    }
    if (e < e1) {
        int s0 = src[e];
        const float* r0 = fs + (size_t)s0 * LD + h * DH;
        float f00 = r0[d0];
        float f01 = b1 ? r0[d1] : 0.f;
        float u0 = f00 + fd0; u0 = u0 > 0.f ? u0 : SLP * u0;
        float w0 = f01 + fd1; w0 = w0 > 0.f ? w0 : SLP * w0;
        float l0 = u0 * a0 + w0 * a1;
#pragma unroll
        for (int o = 16; o; o >>= 1) l0 += __shfl_xor_sync(0xffffffffu, l0, o);
        float nm = fmaxf(m, l0);
        float sc = __expf(m - nm);
        float w0e = __expf(l0 - nm);
        ssum = ssum * sc + w0e;
        acc0 = acc0 * sc + w0e * f00;
        acc1 = acc1 * sc + w0e * f01;
        m = nm;
    }
    float inv = (e1 > e0) ? 1.f / ssum : 0.f;
    {
        float v = acc0 * inv + res[nb + d0];
        if (RELU) v = fmaxf(v, 0.f);
        out[nb + d0] = v;
    }
    if (b1) {
        float v = acc1 * inv + res[nb + d1];
        if (RELU) v = fmaxf(v, 0.f);
        out[nb + d1] = v;
    }
}

// ---------------- BatchNorm (training-mode batch stats) ----------------
__global__ void zero_stats() {
    int i = threadIdx.x;
    if (i < 2 * HD) g_stats[i] = 0.f;
}

__global__ void bn_stats(const float* __restrict__ x) {
    int c = threadIdx.x;            // 128 threads = columns
    int per = (NN + gridDim.x - 1) / gridDim.x;
    int r0 = blockIdx.x * per;
    int r1 = min(NN, r0 + per);
    float s = 0.f, q = 0.f;
    for (int r = r0; r < r1; r++) {
        float v = x[(size_t)r * HD + c];
        s += v; q += v * v;
    }
    atomicAdd(&g_stats[c], s);
    atomicAdd(&g_stats[HD + c], q);
}

__global__ void bn_apply(const float* __restrict__ x, const float* __restrict__ g,
                         const float* __restrict__ b, float* __restrict__ out) {
    size_t i = (size_t)blockIdx.x * blockDim.x + threadIdx.x;
    if (i >= (size_t)NN * HD) return;
    int c = (int)(i & (HD - 1));
    float mu = g_stats[c] * (1.f / NN);
    float var = g_stats[HD + c] * (1.f / NN) - mu * mu;
    float v = g[c] * (x[i] - mu) * rsqrtf(var + EPSI) + b[c];
    out[i] = fmaxf(v, 0.f);
}

// ---------------- head mean + log_softmax (warp per node) ----------------
__global__ void final_logsoftmax(const float* __restrict__ h, float* __restrict__ out) {
    int n = blockIdx.x * (blockDim.x >> 5) + (threadIdx.x >> 5);
    int lane = threadIdx.x & 31;
    if (n >= NN) return;
    const float* row = h + (size_t)n * HC;
    int c0 = lane, c1 = lane + 32;
    bool a0 = c0 < CC, a1 = c1 < CC;
    float v0 = 0.f, v1 = 0.f;
    if (a0) v0 = 0.25f * (row[c0] + row[CC + c0] + row[2 * CC + c0] + row[3 * CC + c0]);
    if (a1) v1 = 0.25f * (row[c1] + row[CC + c1] + row[2 * CC + c1] + row[3 * CC + c1]);
    float mx = fmaxf(a0 ? v0 : -INFINITY, a1 ? v1 : -INFINITY);
#pragma unroll
    for (int o = 16; o; o >>= 1) mx = fmaxf(mx, __shfl_xor_sync(0xffffffffu, mx, o));
    float s = (a0 ? __expf(v0 - mx) : 0.f) + (a1 ? __expf(v1 - mx) : 0.f);
#pragma unroll
    for (int o = 16; o; o >>= 1) s += __shfl_xor_sync(0xffffffffu, s, o);
    float ls = logf(s);
    if (a0) out[(size_t)n * CC + c0] = v0 - mx - ls;
    if (a1) out[(size_t)n * CC + c1] = v1 - mx - ls;
}

extern "C" void kernel_launch(void* const* d_in, const int* in_sizes, int n_in,
                              void* d_out, int out_size) {
    const float* x     = (const float*)d_in[0];
    const int*   src   = (const int*)d_in[1];
    const int*   dst   = (const int*)d_in[2];
    const float* Wsrc0 = (const float*)d_in[3];
    const float* bsrc0 = (const float*)d_in[4];
    const float* Wdst0 = (const float*)d_in[5];
    const float* bdst0 = (const float*)d_in[6];
    const float* attn0 = (const float*)d_in[7];
    const float* Wres0 = (const float*)d_in[8];
    const float* bres0 = (const float*)d_in[9];
    const float* Wsrc1 = (const float*)d_in[10];
    const float* bsrc1 = (const float*)d_in[11];
    const float* Wdst1 = (const float*)d_in[12];
    const float* bdst1 = (const float*)d_in[13];
    const float* attn1 = (const float*)d_in[14];
    const float* Wsrc2 = (const float*)d_in[15];
    const float* bsrc2 = (const float*)d_in[16];
    const float* Wdst2 = (const float*)d_in[17];
    const float* bdst2 = (const float*)d_in[18];
    const float* attn2 = (const float*)d_in[19];
    const float* Wres2 = (const float*)d_in[20];
    const float* bres2 = (const float*)d_in[21];
    const float* g0    = (const float*)d_in[22];
    const float* be0   = (const float*)d_in[23];
    const float* g1    = (const float*)d_in[24];
    const float* be1   = (const float*)d_in[25];
    float* out = (float*)d_out;

    float *fs, *fd, *res, *tmp, *h;
    int* rowptr;
    cudaGetSymbolAddress((void**)&fs, g_fs);
    cudaGetSymbolAddress((void**)&fd, g_fd);
    cudaGetSymbolAddress((void**)&res, g_res);
    cudaGetSymbolAddress((void**)&tmp, g_tmp);
    cudaGetSymbolAddress((void**)&h, g_h);
    cudaGetSymbolAddress((void**)&rowptr, g_rowptr);

    rowptr_kernel<<<(NN + 1 + 255) / 256, 256>>>(dst, rowptr);

    const int my = (NN + BM - 1) / BM;                   // 782
    const int node_grid = (NN * HH + 7) / 8;             // warp/(node,head)
    const int bn_elems_grid = (int)(((size_t)NN * HD + 255) / 256);

    // ---- layer 0: x[100k,100] -> 128, Linear residual (3 outputs, 1 launch) ----
    gemm_bias3<<<dim3(3, my), 256>>>(x, Wsrc0, Wdst0, Wres0, bsrc0, bdst0, bres0,
                                     fs, fd, res, NN, IND, HD, 1);
    gat_fused<DD, true><<<node_grid, 256>>>(fs, fd, attn0, src, rowptr, res, tmp);
    zero_stats<<<1, 256>>>();
    bn_stats<<<2048, 128>>>(tmp);
    bn_apply<<<bn_elems_grid, 256>>>(tmp, g0, be0, h);

    // ---- layer 1: 128 -> 128, Identity residual (2 outputs, 1 launch) ----
    gemm_bias3<<<dim3(2, my), 256>>>(h, Wsrc1, Wdst1, Wdst1, bsrc1, bdst1, bdst1,
                                     fs, fd, fd, NN, HD, HD, 1);
    gat_fused<DD, true><<<node_grid, 256>>>(fs, fd, attn1, src, rowptr, h, tmp);
    zero_stats<<<1, 256>>>();
    bn_stats<<<2048, 128>>>(tmp);
    bn_apply<<<bn_elems_grid, 256>>>(tmp, g1, be1, h);

    // ---- layer 2: 128 -> 188, Linear residual, no BN (3 outputs x 2 col tiles) ----
    gemm_bias3<<<dim3(6, my), 256>>>(h, Wsrc2, Wdst2, Wres2, bsrc2, bdst2, bres2,
                                     fs, fd, res, NN, HD, HC, 2);
    gat_fused<CC, false><<<node_grid, 256>>>(fs, fd, attn2, src, rowptr, res, tmp);

    final_logsoftmax<<<(NN + 7) / 8, 256>>>(tmp, out);
}

// round 4
// speedup vs baseline: 2.4108x; 1.2130x over previous
#include <cuda_runtime.h>
#include <math.h>

#define NN 100000
#define EE 1000000
#define IND 100
#define HH 4
#define DD 32
#define CC 47
#define HD 128
#define HC 188
#define EPSI 1e-5f
#define SLP 0.2f

// ---------------- scratch (static device memory; no allocation) ----------------
__device__ float g_fs[(size_t)NN * HC];
__device__ float g_fd[(size_t)NN * HC];
__device__ float g_res[(size_t)NN * HC];
__device__ float g_tmp[(size_t)NN * HC];
__device__ float g_tmp2[(size_t)NN * HD];
__device__ int   g_rowptr[NN + 1];
__device__ float g_stats[2 * HD];
__device__ float g_sc0[HD], g_sh0[HD], g_sc1[HD], g_sh1[HD];

// ---------------- CSR row_ptr from sorted dst (also zeroes BN stats) ----------------
__global__ void rowptr_kernel(const int* __restrict__ dst, int* __restrict__ rowptr) {
    int n = blockIdx.x * blockDim.x + threadIdx.x;
    if (blockIdx.x == 0 && threadIdx.x < 2 * HD) g_stats[threadIdx.x] = 0.f;
    if (n > NN) return;
    int lo = 0, hi = EE;
    while (lo < hi) {
        int mid = (lo + hi) >> 1;
        if (dst[mid] < n) lo = mid + 1; else hi = mid;
    }
    rowptr[n] = lo;
}

// ---------------- SGEMM: 128x128 tile, 8x8 micro-tile, double-buffered ----------------
// Packs up to 3 outputs (same A, different W/bias/C) into one launch.
// Optional per-column affine+relu (fused BatchNorm) applied to A on load.
#define BM 128
#define BN 128
#define BK 16

__device__ __forceinline__ float4 ldA(const float4* __restrict__ A4, int gm, int gk,
                                      int M, int K, int K4,
                                      const float* __restrict__ bnsc,
                                      const float* __restrict__ bnsh) {
    float4 a = make_float4(0.f, 0.f, 0.f, 0.f);
    if (gm < M && gk < K) {
        a = A4[(size_t)gm * K4 + (gk >> 2)];
        if (bnsc) {
            float4 s = *(const float4*)&bnsc[gk];
            float4 t = *(const float4*)&bnsh[gk];
            a.x = fmaxf(fmaf(a.x, s.x, t.x), 0.f);
            a.y = fmaxf(fmaf(a.y, s.y, t.y), 0.f);
            a.z = fmaxf(fmaf(a.z, s.z, t.z), 0.f);
            a.w = fmaxf(fmaf(a.w, s.w, t.w), 0.f);
        }
    }
    return a;
}

__global__ __launch_bounds__(256) void gemm_bias3(
    const float* __restrict__ A,
    const float* __restrict__ W0, const float* __restrict__ W1, const float* __restrict__ W2,
    const float* __restrict__ b0p, const float* __restrict__ b1p, const float* __restrict__ b2p,
    float* __restrict__ C0, float* __restrict__ C1, float* __restrict__ C2,
    int M, int K, int Nc, int tilesPer,
    const float* __restrict__ bnsc, const float* __restrict__ bnsh) {
    __shared__ float As[2][BK][BM + 4];
    __shared__ float Bs[2][BK][BN + 8];

    int which = blockIdx.x / tilesPer;
    int xt = blockIdx.x - which * tilesPer;
    const float* W = which == 0 ? W0 : (which == 1 ? W1 : W2);
    const float* bias = which == 0 ? b0p : (which == 1 ? b1p : b2p);
    float* C = which == 0 ? C0 : (which == 1 ? C1 : C2);

    int bm = blockIdx.y * BM, bn = xt * BN;
    int tid = threadIdx.x;
    int tx = tid & 15, ty = tid >> 4;

    float acc[8][8];
#pragma unroll
    for (int i = 0; i < 8; i++)
#pragma unroll
        for (int j = 0; j < 8; j++) acc[i][j] = 0.f;

    const float4* A4 = (const float4*)A;
    const float4* W4 = (const float4*)W;
    int K4 = K >> 2, Nc4 = Nc >> 2;
    int T = (K + BK - 1) / BK;

    float4 rA[2], rB[2];

    // prologue: load tile 0
#pragma unroll
    for (int i = 0; i < 2; i++) {
        int idx = tid + i * 256;
        int m = idx >> 2, kq = idx & 3;
        rA[i] = ldA(A4, bm + m, kq * 4, M, K, K4, bnsc, bnsh);
    }
#pragma unroll
    for (int i = 0; i < 2; i++) {
        int idx = tid + i * 256;
        int k = idx >> 5, nq = idx & 31;
        int gn = bn + nq * 4;
        rB[i] = make_float4(0.f, 0.f, 0.f, 0.f);
        if (k < K && gn < Nc) rB[i] = W4[(size_t)k * Nc4 + (gn >> 2)];
    }
#pragma unroll
    for (int i = 0; i < 2; i++) {
        int idx = tid + i * 256;
        int m = idx >> 2, kq = idx & 3;
        As[0][kq * 4 + 0][m] = rA[i].x;
        As[0][kq * 4 + 1][m] = rA[i].y;
        As[0][kq * 4 + 2][m] = rA[i].z;
        As[0][kq * 4 + 3][m] = rA[i].w;
    }
#pragma unroll
    for (int i = 0; i < 2; i++) {
        int idx = tid + i * 256;
        int k = idx >> 5, nq = idx & 31;
        *(float4*)&Bs[0][k][nq * 4] = rB[i];
    }
    __syncthreads();

    for (int t = 0; t < T; t++) {
        int cur = t & 1;
        if (t + 1 < T) {
            int k0 = (t + 1) * BK;
#pragma unroll
            for (int i = 0; i < 2; i++) {
                int idx = tid + i * 256;
                int m = idx >> 2, kq = idx & 3;
                rA[i] = ldA(A4, bm + m, k0 + kq * 4, M, K, K4, bnsc, bnsh);
            }
#pragma unroll
            for (int i = 0; i < 2; i++) {
                int idx = tid + i * 256;
                int k = idx >> 5, nq = idx & 31;
                int gk = k0 + k, gn = bn + nq * 4;
                rB[i] = make_float4(0.f, 0.f, 0.f, 0.f);
                if (gk < K && gn < Nc) rB[i] = W4[(size_t)gk * Nc4 + (gn >> 2)];
            }
        }
#pragma unroll
        for (int k = 0; k < BK; k++) {
            float4 a0 = *(const float4*)&As[cur][k][ty * 8];
            float4 a1 = *(const float4*)&As[cur][k][ty * 8 + 4];
            float4 c0 = *(const float4*)&Bs[cur][k][tx * 8];
            float4 c1 = *(const float4*)&Bs[cur][k][tx * 8 + 4];
            float av[8] = {a0.x, a0.y, a0.z, a0.w, a1.x, a1.y, a1.z, a1.w};
            float bv[8] = {c0.x, c0.y, c0.z, c0.w, c1.x, c1.y, c1.z, c1.w};
#pragma unroll
            for (int i = 0; i < 8; i++)
#pragma unroll
                for (int j = 0; j < 8; j++) acc[i][j] += av[i] * bv[j];
        }
        if (t + 1 < T) {
            int nxt = (t + 1) & 1;
#pragma unroll
            for (int i = 0; i < 2; i++) {
                int idx = tid + i * 256;
                int m = idx >> 2, kq = idx & 3;
                As[nxt][kq * 4 + 0][m] = rA[i].x;
                As[nxt][kq * 4 + 1][m] = rA[i].y;
                As[nxt][kq * 4 + 2][m] = rA[i].z;
                As[nxt][kq * 4 + 3][m] = rA[i].w;
            }
#pragma unroll
            for (int i = 0; i < 2; i++) {
                int idx = tid + i * 256;
                int k = idx >> 5, nq = idx & 31;
                *(float4*)&Bs[nxt][k][nq * 4] = rB[i];
            }
        }
        __syncthreads();
    }

    // epilogue
    int gn0 = bn + tx * 8;
    int gn1 = gn0 + 4;
    bool cok0 = gn0 + 4 <= Nc, cok1 = gn1 + 4 <= Nc;
    float4 bb0 = make_float4(0.f, 0.f, 0.f, 0.f), bb1 = bb0;
    if (cok0) bb0 = *(const float4*)&bias[gn0];
    if (cok1) bb1 = *(const float4*)&bias[gn1];
#pragma unroll
    for (int i = 0; i < 8; i++) {
        int gm = bm + ty * 8 + i;
        if (gm >= M) break;
        if (cok0) {
            float4 o = make_float4(acc[i][0] + bb0.x, acc[i][1] + bb0.y,
                                   acc[i][2] + bb0.z, acc[i][3] + bb0.w);
            *(float4*)&C[(size_t)gm * Nc + gn0] = o;
        }
        if (cok1) {
            float4 o = make_float4(acc[i][4] + bb1.x, acc[i][5] + bb1.y,
                                   acc[i][6] + bb1.z, acc[i][7] + bb1.w);
            *(float4*)&C[(size_t)gm * Nc + gn1] = o;
        }
    }
}

// ---------------- fused GATv2, LD=128: warp per NODE, all 4 heads, float4 lanes ----------------
// lane q covers floats [4q, 4q+4) of the 128-wide row; head = q >> 3.
template <bool BNRES>
__global__ void gat_fused128(const float4* __restrict__ fs, const float4* __restrict__ fd,
                             const float4* __restrict__ attn,
                             const int* __restrict__ src, const int* __restrict__ rowptr,
                             const float4* __restrict__ res,
                             const float4* __restrict__ bnsc, const float4* __restrict__ bnsh,
                             float4* __restrict__ out) {
    int n = blockIdx.x * (blockDim.x >> 5) + (threadIdx.x >> 5);
    if (n >= NN) return;
    int q = threadIdx.x & 31;

    float4 fdl = fd[(size_t)n * 32 + q];
    float4 al = attn[q];
    int e0 = rowptr[n], e1 = rowptr[n + 1];

    float m = -INFINITY, ssum = 0.f;
    float ax = 0.f, ay = 0.f, az = 0.f, aw = 0.f;
    int e = e0;
    for (; e + 1 < e1; e += 2) {
        int s0 = src[e], s1 = src[e + 1];
        float4 f0 = fs[(size_t)s0 * 32 + q];
        float4 f1 = fs[(size_t)s1 * 32 + q];
        float vx, vy, vz, vw;
        vx = f0.x + fdl.x; vx = vx > 0.f ? vx : SLP * vx;
        vy = f0.y + fdl.y; vy = vy > 0.f ? vy : SLP * vy;
        vz = f0.z + fdl.z; vz = vz > 0.f ? vz : SLP * vz;
        vw = f0.w + fdl.w; vw = vw > 0.f ? vw : SLP * vw;
        float l0 = vx * al.x + vy * al.y + vz * al.z + vw * al.w;
        vx = f1.x + fdl.x; vx = vx > 0.f ? vx : SLP * vx;
        vy = f1.y + fdl.y; vy = vy > 0.f ? vy : SLP * vy;
        vz = f1.z + fdl.z; vz = vz > 0.f ? vz : SLP * vz;
        vw = f1.w + fdl.w; vw = vw > 0.f ? vw : SLP * vw;
        float l1 = vx * al.x + vy * al.y + vz * al.z + vw * al.w;
#pragma unroll
        for (int o = 4; o; o >>= 1) {   // reduce within 8-lane head group
            l0 += __shfl_xor_sync(0xffffffffu, l0, o);
            l1 += __shfl_xor_sync(0xffffffffu, l1, o);
        }
        float nm = fmaxf(m, fmaxf(l0, l1));
        float sc = __expf(m - nm);
        float w0 = __expf(l0 - nm);
        float w1 = __expf(l1 - nm);
        ssum = ssum * sc + w0 + w1;
        ax = ax * sc + w0 * f0.x + w1 * f1.x;
        ay = ay * sc + w0 * f0.y + w1 * f1.y;
        az = az * sc + w0 * f0.z + w1 * f1.z;
        aw = aw * sc + w0 * f0.w + w1 * f1.w;
        m = nm;
    }
    if (e < e1) {
        int s0 = src[e];
        float4 f0 = fs[(size_t)s0 * 32 + q];
        float vx = f0.x + fdl.x; vx = vx > 0.f ? vx : SLP * vx;
        float vy = f0.y + fdl.y; vy = vy > 0.f ? vy : SLP * vy;
        float vz = f0.z + fdl.z; vz = vz > 0.f ? vz : SLP * vz;
        float vw = f0.w + fdl.w; vw = vw > 0.f ? vw : SLP * vw;
        float l0 = vx * al.x + vy * al.y + vz * al.z + vw * al.w;
#pragma unroll
        for (int o = 4; o; o >>= 1) l0 += __shfl_xor_sync(0xffffffffu, l0, o);
        float nm = fmaxf(m, l0);
        float sc = __expf(m - nm);
        float w0 = __expf(l0 - nm);
        ssum = ssum * sc + w0;
        ax = ax * sc + w0 * f0.x;
        ay = ay * sc + w0 * f0.y;
        az = az * sc + w0 * f0.z;
        aw = aw * sc + w0 * f0.w;
        m = nm;
    }
    float inv = (e1 > e0) ? 1.f / ssum : 0.f;
    float4 r = res[(size_t)n * 32 + q];
    if (BNRES) {
        float4 s = bnsc[q], t = bnsh[q];
        r.x = fmaxf(fmaf(r.x, s.x, t.x), 0.f);
        r.y = fmaxf(fmaf(r.y, s.y, t.y), 0.f);
        r.z = fmaxf(fmaf(r.z, s.z, t.z), 0.f);
        r.w = fmaxf(fmaf(r.w, s.w, t.w), 0.f);
    }
    float4 o;
    o.x = fmaxf(ax * inv + r.x, 0.f);
    o.y = fmaxf(ay * inv + r.y, 0.f);
    o.z = fmaxf(az * inv + r.z, 0.f);
    o.w = fmaxf(aw * inv + r.w, 0.f);
    out[(size_t)n * 32 + q] = o;
}

// ---------------- fused GATv2, generic (layer 2, DH=47, no relu) ----------------
template <int DH>
__global__ void gat_fusedN(const float* __restrict__ fs, const float* __restrict__ fd,
                           const float* __restrict__ attn,
                           const int* __restrict__ src, const int* __restrict__ rowptr,
                           const float* __restrict__ res, float* __restrict__ out) {
    const int LD = HH * DH;
    int gw = blockIdx.x * (blockDim.x >> 5) + (threadIdx.x >> 5);
    if (gw >= NN * HH) return;
    int n = gw >> 2, h = gw & 3;
    int lane = threadIdx.x & 31;
    int d0 = lane, d1 = lane + 32;
    const bool b1 = d1 < DH;

    size_t nb = (size_t)n * LD + h * DH;
    float fd0 = fd[nb + d0];
    float a0 = attn[h * DH + d0];
    float fd1 = b1 ? fd[nb + d1] : 0.f;
    float a1 = b1 ? attn[h * DH + d1] : 0.f;

    int e0 = rowptr[n], e1 = rowptr[n + 1];
    float m = -INFINITY, ssum = 0.f, acc0 = 0.f, acc1 = 0.f;
    int e = e0;
    for (; e + 1 < e1; e += 2) {
        int s0 = src[e], s1 = src[e + 1];
        const float* r0 = fs + (size_t)s0 * LD + h * DH;
        const float* r1 = fs + (size_t)s1 * LD + h * DH;
        float f00 = r0[d0];
        float f10 = r1[d0];
        float f01 = b1 ? r0[d1] : 0.f;
        float f11 = b1 ? r1[d1] : 0.f;
        float u0 = f00 + fd0; u0 = u0 > 0.f ? u0 : SLP * u0;
        float w0 = f01 + fd1; w0 = w0 > 0.f ? w0 : SLP * w0;
        float u1 = f10 + fd0; u1 = u1 > 0.f ? u1 : SLP * u1;
        float w1 = f11 + fd1; w1 = w1 > 0.f ? w1 : SLP * w1;
        float l0 = u0 * a0 + w0 * a1;
        float l1 = u1 * a0 + w1 * a1;
#pragma unroll
        for (int o = 16; o; o >>= 1) {
            l0 += __shfl_xor_sync(0xffffffffu, l0, o);
            l1 += __shfl_xor_sync(0xffffffffu, l1, o);
        }
        float nm = fmaxf(m, fmaxf(l0, l1));
        float sc = __expf(m - nm);
        float w0e = __expf(l0 - nm);
        float w1e = __expf(l1 - nm);
        ssum = ssum * sc + w0e + w1e;
        acc0 = acc0 * sc + w0e * f00 + w1e * f10;
        acc1 = acc1 * sc + w0e * f01 + w1e * f11;
        m = nm;
    }
    if (e < e1) {
        int s0 = src[e];
        const float* r0 = fs + (size_t)s0 * LD + h * DH;
        float f00 = r0[d0];
        float f01 = b1 ? r0[d1] : 0.f;
        float u0 = f00 + fd0; u0 = u0 > 0.f ? u0 : SLP * u0;
        float w0 = f01 + fd1; w0 = w0 > 0.f ? w0 : SLP * w0;
        float l0 = u0 * a0 + w0 * a1;
#pragma unroll
        for (int o = 16; o; o >>= 1) l0 += __shfl_xor_sync(0xffffffffu, l0, o);
        float nm = fmaxf(m, l0);
        float sc = __expf(m - nm);
        float w0e = __expf(l0 - nm);
        ssum = ssum * sc + w0e;
        acc0 = acc0 * sc + w0e * f00;
        acc1 = acc1 * sc + w0e * f01;
        m = nm;
    }
    float inv = (e1 > e0) ? 1.f / ssum : 0.f;
    out[nb + d0] = acc0 * inv + res[nb + d0];
    if (b1) out[nb + d1] = acc1 * inv + res[nb + d1];
}

// ---------------- BatchNorm stats + finalize ----------------
__global__ void bn_stats(const float* __restrict__ x) {
    int c = threadIdx.x;            // 128 threads = columns
    int per = (NN + gridDim.x - 1) / gridDim.x;
    int r0 = blockIdx.x * per;
    int r1 = min(NN, r0 + per);
    float s = 0.f, q = 0.f;
    for (int r = r0; r < r1; r++) {
        float v = x[(size_t)r * HD + c];
        s += v; q += v * v;
    }
    atomicAdd(&g_stats[c], s);
    atomicAdd(&g_stats[HD + c], q);
}

// computes per-channel affine from stats, then re-zeros stats for next use
__global__ void bn_finalize(const float* __restrict__ g, const float* __restrict__ b,
                            float* __restrict__ sc, float* __restrict__ sh) {
    int c = threadIdx.x;  // 128
    float mu = g_stats[c] * (1.f / NN);
    float var = g_stats[HD + c] * (1.f / NN) - mu * mu;
    float s = g[c] * rsqrtf(var + EPSI);
    sc[c] = s;
    sh[c] = b[c] - mu * s;
    g_stats[c] = 0.f;
    g_stats[HD + c] = 0.f;
}

// ---------------- head mean + log_softmax (warp per node) ----------------
__global__ void final_logsoftmax(const float* __restrict__ h, float* __restrict__ out) {
    int n = blockIdx.x * (blockDim.x >> 5) + (threadIdx.x >> 5);
    int lane = threadIdx.x & 31;
    if (n >= NN) return;
    const float* row = h + (size_t)n * HC;
    int c0 = lane, c1 = lane + 32;
    bool a0 = c0 < CC, a1 = c1 < CC;
    float v0 = 0.f, v1 = 0.f;
    if (a0) v0 = 0.25f * (row[c0] + row[CC + c0] + row[2 * CC + c0] + row[3 * CC + c0]);
    if (a1) v1 = 0.25f * (row[c1] + row[CC + c1] + row[2 * CC + c1] + row[3 * CC + c1]);
    float mx = fmaxf(a0 ? v0 : -INFINITY, a1 ? v1 : -INFINITY);
#pragma unroll
    for (int o = 16; o; o >>= 1) mx = fmaxf(mx, __shfl_xor_sync(0xffffffffu, mx, o));
    float s = (a0 ? __expf(v0 - mx) : 0.f) + (a1 ? __expf(v1 - mx) : 0.f);
#pragma unroll
    for (int o = 16; o; o >>= 1) s += __shfl_xor_sync(0xffffffffu, s, o);
    float ls = logf(s);
    if (a0) out[(size_t)n * CC + c0] = v0 - mx - ls;
    if (a1) out[(size_t)n * CC + c1] = v1 - mx - ls;
}

extern "C" void kernel_launch(void* const* d_in, const int* in_sizes, int n_in,
                              void* d_out, int out_size) {
    const float* x     = (const float*)d_in[0];
    const int*   src   = (const int*)d_in[1];
    const int*   dst   = (const int*)d_in[2];
    const float* Wsrc0 = (const float*)d_in[3];
    const float* bsrc0 = (const float*)d_in[4];
    const float* Wdst0 = (const float*)d_in[5];
    const float* bdst0 = (const float*)d_in[6];
    const float* attn0 = (const float*)d_in[7];
    const float* Wres0 = (const float*)d_in[8];
    const float* bres0 = (const float*)d_in[9];
    const float* Wsrc1 = (const float*)d_in[10];
    const float* bsrc1 = (const float*)d_in[11];
    const float* Wdst1 = (const float*)d_in[12];
    const float* bdst1 = (const float*)d_in[13];
    const float* attn1 = (const float*)d_in[14];
    const float* Wsrc2 = (const float*)d_in[15];
    const float* bsrc2 = (const float*)d_in[16];
    const float* Wdst2 = (const float*)d_in[17];
    const float* bdst2 = (const float*)d_in[18];
    const float* attn2 = (const float*)d_in[19];
    const float* Wres2 = (const float*)d_in[20];
    const float* bres2 = (const float*)d_in[21];
    const float* g0    = (const float*)d_in[22];
    const float* be0   = (const float*)d_in[23];
    const float* g1    = (const float*)d_in[24];
    const float* be1   = (const float*)d_in[25];
    float* out = (float*)d_out;

    float *fs, *fd, *res, *tmp, *tmp2, *sc0, *sh0, *sc1, *sh1;
    int* rowptr;
    cudaGetSymbolAddress((void**)&fs, g_fs);
    cudaGetSymbolAddress((void**)&fd, g_fd);
    cudaGetSymbolAddress((void**)&res, g_res);
    cudaGetSymbolAddress((void**)&tmp, g_tmp);
    cudaGetSymbolAddress((void**)&tmp2, g_tmp2);
    cudaGetSymbolAddress((void**)&rowptr, g_rowptr);
    cudaGetSymbolAddress((void**)&sc0, g_sc0);
    cudaGetSymbolAddress((void**)&sh0, g_sh0);
    cudaGetSymbolAddress((void**)&sc1, g_sc1);
    cudaGetSymbolAddress((void**)&sh1, g_sh1);

    rowptr_kernel<<<(NN + 1 + 255) / 256, 256>>>(dst, rowptr);

    const int my = (NN + BM - 1) / BM;                   // 782
    const int node_grid = (NN + 7) / 8;                  // warp/node (8 warps/block)
    const int nodehead_grid = (NN * HH + 7) / 8;

    // ---- layer 0: x[100k,100] -> 128, Linear residual (3 outputs, 1 launch) ----
    gemm_bias3<<<dim3(3, my), 256>>>(x, Wsrc0, Wdst0, Wres0, bsrc0, bdst0, bres0,
                                     fs, fd, res, NN, IND, HD, 1, nullptr, nullptr);
    gat_fused128<false><<<node_grid, 256>>>((const float4*)fs, (const float4*)fd,
                                            (const float4*)attn0, src, rowptr,
                                            (const float4*)res, nullptr, nullptr,
                                            (float4*)tmp);
    bn_stats<<<2048, 128>>>(tmp);
    bn_finalize<<<1, 128>>>(g0, be0, sc0, sh0);

    // ---- layer 1: A = relu(bn0(tmp)), Identity residual = same ----
    gemm_bias3<<<dim3(2, my), 256>>>(tmp, Wsrc1, Wdst1, Wdst1, bsrc1, bdst1, bdst1,
                                     fs, fd, fd, NN, HD, HD, 1, sc0, sh0);
    gat_fused128<true><<<node_grid, 256>>>((const float4*)fs, (const float4*)fd,
                                           (const float4*)attn1, src, rowptr,
                                           (const float4*)tmp, (const float4*)sc0,
                                           (const float4*)sh0, (float4*)tmp2);
    bn_stats<<<2048, 128>>>(tmp2);
    bn_finalize<<<1, 128>>>(g1, be1, sc1, sh1);

    // ---- layer 2: A = relu(bn1(tmp2)) -> 188, Linear residual, no BN ----
    gemm_bias3<<<dim3(6, my), 256>>>(tmp2, Wsrc2, Wdst2, Wres2, bsrc2, bdst2, bres2,
                                     fs, fd, res, NN, HD, HC, 2, sc1, sh1);
    gat_fusedN<CC><<<nodehead_grid, 256>>>(fs, fd, attn2, src, rowptr, res, tmp);

    final_logsoftmax<<<(NN + 7) / 8, 256>>>(tmp, out);
}

// round 8
// speedup vs baseline: 3.1604x; 1.3109x over previous
#include <cuda_runtime.h>
#include <math.h>
#include <stdint.h>

#define NN 100000
#define EE 1000000
#define IND 100
#define HH 4
#define DD 32
#define CC 47
#define HD 128
#define HC 188
#define EPSI 1e-5f
#define SLP 0.2f

// ---------------- scratch (static device memory; no allocation) ----------------
__device__ float g_fs[(size_t)NN * HC];
__device__ float g_fd[(size_t)NN * HC];
__device__ float g_res[(size_t)NN * HC];
__device__ float g_tmp[(size_t)NN * HC];
__device__ float g_tmp2[(size_t)NN * HD];
__device__ int   g_rowptr[NN + 1];
__device__ float g_stats[2 * HD];
__device__ float g_sc0[HD], g_sh0[HD], g_sc1[HD], g_sh1[HD];

// ---------------- CSR row_ptr from sorted dst (also zeroes BN stats) ----------------
__global__ void rowptr_kernel(const int* __restrict__ dst, int* __restrict__ rowptr) {
    int n = blockIdx.x * blockDim.x + threadIdx.x;
    if (blockIdx.x == 0 && threadIdx.x < 2 * HD) g_stats[threadIdx.x] = 0.f;
    if (n > NN) return;
    int lo = 0, hi = EE;
    while (lo < hi) {
        int mid = (lo + hi) >> 1;
        if (dst[mid] < n) lo = mid + 1; else hi = mid;
    }
    rowptr[n] = lo;
}

// ---------------- tf32 helpers ----------------
__device__ __forceinline__ uint32_t f2tf(float f) {
    uint32_t r;
    asm("cvt.rna.tf32.f32 %0, %1;" : "=r"(r) : "f"(f));
    return r;
}

__device__ __forceinline__ void mma_tf32(float* c, const uint32_t* a, const uint32_t* b) {
    asm volatile(
        "mma.sync.aligned.m16n8k8.row.col.f32.tf32.tf32.f32 "
        "{%0,%1,%2,%3}, {%4,%5,%6,%7}, {%8,%9}, {%0,%1,%2,%3};"
        : "+f"(c[0]), "+f"(c[1]), "+f"(c[2]), "+f"(c[3])
        : "r"(a[0]), "r"(a[1]), "r"(a[2]), "r"(a[3]), "r"(b[0]), "r"(b[1]));
}

// ---------------- tf32 tensor-core GEMM: 128x128 tile, BK=32, 8 warps ----------------
// Packs up to 3 outputs (same A, different W/bias/C); optional BN affine+relu on A.
#define TBM 128
#define TBN 128
#define TBK 32
#define ASTRIDE 36
#define BSTRIDE 136

__device__ __forceinline__ float4 ldA_aff(const float4* __restrict__ A4, int gm, int gk,
                                          int M, int K, int K4,
                                          const float* __restrict__ bnsc,
                                          const float* __restrict__ bnsh) {
    float4 a = make_float4(0.f, 0.f, 0.f, 0.f);
    if (gm < M && gk < K) {
        a = A4[(size_t)gm * K4 + (gk >> 2)];
        if (bnsc) {
            float4 s = *(const float4*)&bnsc[gk];
            float4 t = *(const float4*)&bnsh[gk];
            a.x = fmaxf(fmaf(a.x, s.x, t.x), 0.f);
            a.y = fmaxf(fmaf(a.y, s.y, t.y), 0.f);
            a.z = fmaxf(fmaf(a.z, s.z, t.z), 0.f);
            a.w = fmaxf(fmaf(a.w, s.w, t.w), 0.f);
        }
    }
    return a;
}

__global__ __launch_bounds__(256) void gemm_tc3(
    const float* __restrict__ A,
    const float* __restrict__ W0, const float* __restrict__ W1, const float* __restrict__ W2,
    const float* __restrict__ b0p, const float* __restrict__ b1p, const float* __restrict__ b2p,
    float* __restrict__ C0, float* __restrict__ C1, float* __restrict__ C2,
    int M, int K, int Nc, int tilesPer,
    const float* __restrict__ bnsc, const float* __restrict__ bnsh) {
    __shared__ uint32_t As[TBM][ASTRIDE];   // [m][k], stride 36 -> conflict-free frags
    __shared__ uint32_t Bs[TBK][BSTRIDE];   // [k][n], stride 136 -> conflict-free frags

    int which = blockIdx.x / tilesPer;
    int xt = blockIdx.x - which * tilesPer;
    const float* W = which == 0 ? W0 : (which == 1 ? W1 : W2);
    const float* bias = which == 0 ? b0p : (which == 1 ? b1p : b2p);
    float* C = which == 0 ? C0 : (which == 1 ? C1 : C2);

    int bm = blockIdx.y * TBM, bn = xt * TBN;
    int tid = threadIdx.x;
    int wid = tid >> 5, lane = tid & 31;
    int warpM = wid & 1, warpN = wid >> 1;          // 2 x 4 warps
    int g = lane >> 2, tig = lane & 3;

    float acc[4][4][4];
#pragma unroll
    for (int mi = 0; mi < 4; mi++)
#pragma unroll
        for (int ni = 0; ni < 4; ni++)
#pragma unroll
            for (int r = 0; r < 4; r++) acc[mi][ni][r] = 0.f;

    const float4* A4 = (const float4*)A;
    const float4* W4 = (const float4*)W;
    int K4 = K >> 2, Nc4 = Nc >> 2;
    int T = (K + TBK - 1) / TBK;

    float4 rA[4], rB[4];

    // prologue: load tile 0 into regs
#pragma unroll
    for (int i = 0; i < 4; i++) {
        int idx = tid + i * 256;
        int m = idx >> 3, kq = idx & 7;
        rA[i] = ldA_aff(A4, bm + m, kq * 4, M, K, K4, bnsc, bnsh);
    }
#pragma unroll
    for (int i = 0; i < 4; i++) {
        int idx = tid + i * 256;
        int k = idx >> 5, nq = idx & 31;
        int gn = bn + nq * 4;
        rB[i] = make_float4(0.f, 0.f, 0.f, 0.f);
        if (k < K && gn < Nc) rB[i] = W4[(size_t)k * Nc4 + (gn >> 2)];
    }

    for (int t = 0; t < T; t++) {
        // store regs -> smem (tf32 convert)
#pragma unroll
        for (int i = 0; i < 4; i++) {
            int idx = tid + i * 256;
            int m = idx >> 3, kq = idx & 7;
            As[m][kq * 4 + 0] = f2tf(rA[i].x);
            As[m][kq * 4 + 1] = f2tf(rA[i].y);
            As[m][kq * 4 + 2] = f2tf(rA[i].z);
            As[m][kq * 4 + 3] = f2tf(rA[i].w);
        }
#pragma unroll
        for (int i = 0; i < 4; i++) {
            int idx = tid + i * 256;
            int k = idx >> 5, nq = idx & 31;
            Bs[k][nq * 4 + 0] = f2tf(rB[i].x);
            Bs[k][nq * 4 + 1] = f2tf(rB[i].y);
            Bs[k][nq * 4 + 2] = f2tf(rB[i].z);
            Bs[k][nq * 4 + 3] = f2tf(rB[i].w);
        }
        __syncthreads();

        // prefetch next tile into regs (overlaps with MMA below)
        if (t + 1 < T) {
            int k0 = (t + 1) * TBK;
#pragma unroll
            for (int i = 0; i < 4; i++) {
                int idx = tid + i * 256;
                int m = idx >> 3, kq = idx & 7;
                rA[i] = ldA_aff(A4, bm + m, k0 + kq * 4, M, K, K4, bnsc, bnsh);
            }
#pragma unroll
            for (int i = 0; i < 4; i++) {
                int idx = tid + i * 256;
                int k = idx >> 5, nq = idx & 31;
                int gk = k0 + k, gn = bn + nq * 4;
                rB[i] = make_float4(0.f, 0.f, 0.f, 0.f);
                if (gk < K && gn < Nc) rB[i] = W4[(size_t)gk * Nc4 + (gn >> 2)];
            }
        }

        // compute: 4 k-steps of m16n8k8
#pragma unroll
        for (int ks = 0; ks < 4; ks++) {
            int Ck = ks * 8;
            uint32_t af[4][4];
#pragma unroll
            for (int mi = 0; mi < 4; mi++) {
                int r = warpM * 64 + mi * 16;
                af[mi][0] = As[r + g][Ck + tig];
                af[mi][1] = As[r + g + 8][Ck + tig];
                af[mi][2] = As[r + g][Ck + tig + 4];
                af[mi][3] = As[r + g + 8][Ck + tig + 4];
            }
            uint32_t bf[4][2];
#pragma unroll
            for (int ni = 0; ni < 4; ni++) {
                int c = warpN * 32 + ni * 8;
                bf[ni][0] = Bs[Ck + tig][c + g];
                bf[ni][1] = Bs[Ck + tig + 4][c + g];
            }
#pragma unroll
            for (int mi = 0; mi < 4; mi++)
#pragma unroll
                for (int ni = 0; ni < 4; ni++)
                    mma_tf32(acc[mi][ni], af[mi], bf[ni]);
        }
        __syncthreads();
    }

    // epilogue: c0,c1 at (row g, cols 2tig..2tig+1), c2,c3 at row g+8
#pragma unroll
    for (int ni = 0; ni < 4; ni++) {
        int gn = bn + warpN * 32 + ni * 8 + 2 * tig;
        if (gn + 1 >= Nc && gn >= Nc) continue;
        float2 bb = *(const float2*)&bias[gn];
#pragma unroll
        for (int mi = 0; mi < 4; mi++) {
            int gm = bm + warpM * 64 + mi * 16 + g;
            if (gm < M) {
                float2 o = make_float2(acc[mi][ni][0] + bb.x, acc[mi][ni][1] + bb.y);
                *(float2*)&C[(size_t)gm * Nc + gn] = o;
            }
            if (gm + 8 < M) {
                float2 o = make_float2(acc[mi][ni][2] + bb.x, acc[mi][ni][3] + bb.y);
                *(float2*)&C[(size_t)(gm + 8) * Nc + gn] = o;
            }
        }
    }
}

// ---------------- fused GATv2, LD=128: warp per NODE, all 4 heads, float4 lanes ----------------
template <bool BNRES>
__global__ void gat_fused128(const float4* __restrict__ fs, const float4* __restrict__ fd,
                             const float4* __restrict__ attn,
                             const int* __restrict__ src, const int* __restrict__ rowptr,
                             const float4* __restrict__ res,
                             const float4* __restrict__ bnsc, const float4* __restrict__ bnsh,
                             float4* __restrict__ out) {
    int n = blockIdx.x * (blockDim.x >> 5) + (threadIdx.x >> 5);
    if (n >= NN) return;
    int q = threadIdx.x & 31;

    float4 fdl = fd[(size_t)n * 32 + q];
    float4 al = attn[q];
    int e0 = rowptr[n], e1 = rowptr[n + 1];

    float m = -INFINITY, ssum = 0.f;
    float ax = 0.f, ay = 0.f, az = 0.f, aw = 0.f;
    int e = e0;
    for (; e + 1 < e1; e += 2) {
        int s0 = src[e], s1 = src[e + 1];
        float4 f0 = fs[(size_t)s0 * 32 + q];
        float4 f1 = fs[(size_t)s1 * 32 + q];
        float vx, vy, vz, vw;
        vx = f0.x + fdl.x; vx = vx > 0.f ? vx : SLP * vx;
        vy = f0.y + fdl.y; vy = vy > 0.f ? vy : SLP * vy;
        vz = f0.z + fdl.z; vz = vz > 0.f ? vz : SLP * vz;
        vw = f0.w + fdl.w; vw = vw > 0.f ? vw : SLP * vw;
        float l0 = vx * al.x + vy * al.y + vz * al.z + vw * al.w;
        vx = f1.x + fdl.x; vx = vx > 0.f ? vx : SLP * vx;
        vy = f1.y + fdl.y; vy = vy > 0.f ? vy : SLP * vy;
        vz = f1.z + fdl.z; vz = vz > 0.f ? vz : SLP * vz;
        vw = f1.w + fdl.w; vw = vw > 0.f ? vw : SLP * vw;
        float l1 = vx * al.x + vy * al.y + vz * al.z + vw * al.w;
#pragma unroll
        for (int o = 4; o; o >>= 1) {
            l0 += __shfl_xor_sync(0xffffffffu, l0, o);
            l1 += __shfl_xor_sync(0xffffffffu, l1, o);
        }
        float nm = fmaxf(m, fmaxf(l0, l1));
        float sc = __expf(m - nm);
        float w0 = __expf(l0 - nm);
        float w1 = __expf(l1 - nm);
        ssum = ssum * sc + w0 + w1;
        ax = ax * sc + w0 * f0.x + w1 * f1.x;
        ay = ay * sc + w0 * f0.y + w1 * f1.y;
        az = az * sc + w0 * f0.z + w1 * f1.z;
        aw = aw * sc + w0 * f0.w + w1 * f1.w;
        m = nm;
    }
    if (e < e1) {
        int s0 = src[e];
        float4 f0 = fs[(size_t)s0 * 32 + q];
        float vx = f0.x + fdl.x; vx = vx > 0.f ? vx : SLP * vx;
        float vy = f0.y + fdl.y; vy = vy > 0.f ? vy : SLP * vy;
        float vz = f0.z + fdl.z; vz = vz > 0.f ? vz : SLP * vz;
        float vw = f0.w + fdl.w; vw = vw > 0.f ? vw : SLP * vw;
        float l0 = vx * al.x + vy * al.y + vz * al.z + vw * al.w;
#pragma unroll
        for (int o = 4; o; o >>= 1) l0 += __shfl_xor_sync(0xffffffffu, l0, o);
        float nm = fmaxf(m, l0);
        float sc = __expf(m - nm);
        float w0 = __expf(l0 - nm);
        ssum = ssum * sc + w0;
        ax = ax * sc + w0 * f0.x;
        ay = ay * sc + w0 * f0.y;
        az = az * sc + w0 * f0.z;
        aw = aw * sc + w0 * f0.w;
        m = nm;
    }
    float inv = (e1 > e0) ? 1.f / ssum : 0.f;
    float4 r = res[(size_t)n * 32 + q];
    if (BNRES) {
        float4 s = bnsc[q], t = bnsh[q];
        r.x = fmaxf(fmaf(r.x, s.x, t.x), 0.f);
        r.y = fmaxf(fmaf(r.y, s.y, t.y), 0.f);
        r.z = fmaxf(fmaf(r.z, s.z, t.z), 0.f);
        r.w = fmaxf(fmaf(r.w, s.w, t.w), 0.f);
    }
    float4 o;
    o.x = fmaxf(ax * inv + r.x, 0.f);
    o.y = fmaxf(ay * inv + r.y, 0.f);
    o.z = fmaxf(az * inv + r.z, 0.f);
    o.w = fmaxf(aw * inv + r.w, 0.f);
    out[(size_t)n * 32 + q] = o;
}

// ---------------- fused GATv2, generic (layer 2, DH=47, no relu) ----------------
template <int DH>
__global__ void gat_fusedN(const float* __restrict__ fs, const float* __restrict__ fd,
                           const float* __restrict__ attn,
                           const int* __restrict__ src, const int* __restrict__ rowptr,
                           const float* __restrict__ res, float* __restrict__ out) {
    const int LD = HH * DH;
    int gw = blockIdx.x * (blockDim.x >> 5) + (threadIdx.x >> 5);
    if (gw >= NN * HH) return;
    int n = gw >> 2, h = gw & 3;
    int lane = threadIdx.x & 31;
    int d0 = lane, d1 = lane + 32;
    const bool b1 = d1 < DH;

    size_t nb = (size_t)n * LD + h * DH;
    float fd0 = fd[nb + d0];
    float a0 = attn[h * DH + d0];
    float fd1 = b1 ? fd[nb + d1] : 0.f;
    float a1 = b1 ? attn[h * DH + d1] : 0.f;

    int e0 = rowptr[n], e1 = rowptr[n + 1];
    float m = -INFINITY, ssum = 0.f, acc0 = 0.f, acc1 = 0.f;
    int e = e0;
    for (; e + 1 < e1; e += 2) {
        int s0 = src[e], s1 = src[e + 1];
        const float* r0 = fs + (size_t)s0 * LD + h * DH;
        const float* r1 = fs + (size_t)s1 * LD + h * DH;
        float f00 = r0[d0];
        float f10 = r1[d0];
        float f01 = b1 ? r0[d1] : 0.f;
        float f11 = b1 ? r1[d1] : 0.f;
        float u0 = f00 + fd0; u0 = u0 > 0.f ? u0 : SLP * u0;
        float w0 = f01 + fd1; w0 = w0 > 0.f ? w0 : SLP * w0;
        float u1 = f10 + fd0; u1 = u1 > 0.f ? u1 : SLP * u1;
        float w1 = f11 + fd1; w1 = w1 > 0.f ? w1 : SLP * w1;
        float l0 = u0 * a0 + w0 * a1;
        float l1 = u1 * a0 + w1 * a1;
#pragma unroll
        for (int o = 16; o; o >>= 1) {
            l0 += __shfl_xor_sync(0xffffffffu, l0, o);
            l1 += __shfl_xor_sync(0xffffffffu, l1, o);
        }
        float nm = fmaxf(m, fmaxf(l0, l1));
        float sc = __expf(m - nm);
        float w0e = __expf(l0 - nm);
        float w1e = __expf(l1 - nm);
        ssum = ssum * sc + w0e + w1e;
        acc0 = acc0 * sc + w0e * f00 + w1e * f10;
        acc1 = acc1 * sc + w0e * f01 + w1e * f11;
        m = nm;
    }
    if (e < e1) {
        int s0 = src[e];
        const float* r0 = fs + (size_t)s0 * LD + h * DH;
        float f00 = r0[d0];
        float f01 = b1 ? r0[d1] : 0.f;
        float u0 = f00 + fd0; u0 = u0 > 0.f ? u0 : SLP * u0;
        float w0 = f01 + fd1; w0 = w0 > 0.f ? w0 : SLP * w0;
        float l0 = u0 * a0 + w0 * a1;
#pragma unroll
        for (int o = 16; o; o >>= 1) l0 += __shfl_xor_sync(0xffffffffu, l0, o);
        float nm = fmaxf(m, l0);
        float sc = __expf(m - nm);
        float w0e = __expf(l0 - nm);
        ssum = ssum * sc + w0e;
        acc0 = acc0 * sc + w0e * f00;
        acc1 = acc1 * sc + w0e * f01;
        m = nm;
    }
    float inv = (e1 > e0) ? 1.f / ssum : 0.f;
    out[nb + d0] = acc0 * inv + res[nb + d0];
    if (b1) out[nb + d1] = acc1 * inv + res[nb + d1];
}

// ---------------- BatchNorm stats + finalize ----------------
__global__ void bn_stats(const float* __restrict__ x) {
    int c = threadIdx.x;            // 128 threads = columns
    int per = (NN + gridDim.x - 1) / gridDim.x;
    int r0 = blockIdx.x * per;
    int r1 = min(NN, r0 + per);
    float s = 0.f, q = 0.f;
    int r = r0;
    for (; r + 3 < r1; r += 4) {
        float v0 = x[(size_t)r * HD + c];
        float v1 = x[(size_t)(r + 1) * HD + c];
        float v2 = x[(size_t)(r + 2) * HD + c];
        float v3 = x[(size_t)(r + 3) * HD + c];
        s += (v0 + v1) + (v2 + v3);
        q += (v0 * v0 + v1 * v1) + (v2 * v2 + v3 * v3);
    }
    for (; r < r1; r++) {
        float v = x[(size_t)r * HD + c];
        s += v; q += v * v;
    }
    atomicAdd(&g_stats[c], s);
    atomicAdd(&g_stats[HD + c], q);
}

__global__ void bn_finalize(const float* __restrict__ g, const float* __restrict__ b,
                            float* __restrict__ sc, float* __restrict__ sh) {
    int c = threadIdx.x;  // 128
    float mu = g_stats[c] * (1.f / NN);
    float var = g_stats[HD + c] * (1.f / NN) - mu * mu;
    float s = g[c] * rsqrtf(var + EPSI);
    sc[c] = s;
    sh[c] = b[c] - mu * s;
    g_stats[c] = 0.f;
    g_stats[HD + c] = 0.f;
}

// ---------------- head mean + log_softmax (warp per node) ----------------
__global__ void final_logsoftmax(const float* __restrict__ h, float* __restrict__ out) {
    int n = blockIdx.x * (blockDim.x >> 5) + (threadIdx.x >> 5);
    int lane = threadIdx.x & 31;
    if (n >= NN) return;
    const float* row = h + (size_t)n * HC;
    int c0 = lane, c1 = lane + 32;
    bool a0 = c0 < CC, a1 = c1 < CC;
    float v0 = 0.f, v1 = 0.f;
    if (a0) v0 = 0.25f * (row[c0] + row[CC + c0] + row[2 * CC + c0] + row[3 * CC + c0]);
    if (a1) v1 = 0.25f * (row[c1] + row[CC + c1] + row[2 * CC + c1] + row[3 * CC + c1]);
    float mx = fmaxf(a0 ? v0 : -INFINITY, a1 ? v1 : -INFINITY);
#pragma unroll
    for (int o = 16; o; o >>= 1) mx = fmaxf(mx, __shfl_xor_sync(0xffffffffu, mx, o));
    float s = (a0 ? __expf(v0 - mx) : 0.f) + (a1 ? __expf(v1 - mx) : 0.f);
#pragma unroll
    for (int o = 16; o; o >>= 1) s += __shfl_xor_sync(0xffffffffu, s, o);
    float ls = logf(s);
    if (a0) out[(size_t)n * CC + c0] = v0 - mx - ls;
    if (a1) out[(size_t)n * CC + c1] = v1 - mx - ls;
}

extern "C" void kernel_launch(void* const* d_in, const int* in_sizes, int n_in,
                              void* d_out, int out_size) {
    const float* x     = (const float*)d_in[0];
    const int*   src   = (const int*)d_in[1];
    const int*   dst   = (const int*)d_in[2];
    const float* Wsrc0 = (const float*)d_in[3];
    const float* bsrc0 = (const float*)d_in[4];
    const float* Wdst0 = (const float*)d_in[5];
    const float* bdst0 = (const float*)d_in[6];
    const float* attn0 = (const float*)d_in[7];
    const float* Wres0 = (const float*)d_in[8];
    const float* bres0 = (const float*)d_in[9];
    const float* Wsrc1 = (const float*)d_in[10];
    const float* bsrc1 = (const float*)d_in[11];
    const float* Wdst1 = (const float*)d_in[12];
    const float* bdst1 = (const float*)d_in[13];
    const float* attn1 = (const float*)d_in[14];
    const float* Wsrc2 = (const float*)d_in[15];
    const float* bsrc2 = (const float*)d_in[16];
    const float* Wdst2 = (const float*)d_in[17];
    const float* bdst2 = (const float*)d_in[18];
    const float* attn2 = (const float*)d_in[19];
    const float* Wres2 = (const float*)d_in[20];
    const float* bres2 = (const float*)d_in[21];
    const float* g0    = (const float*)d_in[22];
    const float* be0   = (const float*)d_in[23];
    const float* g1    = (const float*)d_in[24];
    const float* be1   = (const float*)d_in[25];
    float* out = (float*)d_out;

    float *fs, *fd, *res, *tmp, *tmp2, *sc0, *sh0, *sc1, *sh1;
    int* rowptr;
    cudaGetSymbolAddress((void**)&fs, g_fs);
    cudaGetSymbolAddress((void**)&fd, g_fd);
    cudaGetSymbolAddress((void**)&res, g_res);
    cudaGetSymbolAddress((void**)&tmp, g_tmp);
    cudaGetSymbolAddress((void**)&tmp2, g_tmp2);
    cudaGetSymbolAddress((void**)&rowptr, g_rowptr);
    cudaGetSymbolAddress((void**)&sc0, g_sc0);
    cudaGetSymbolAddress((void**)&sh0, g_sh0);
    cudaGetSymbolAddress((void**)&sc1, g_sc1);
    cudaGetSymbolAddress((void**)&sh1, g_sh1);

    rowptr_kernel<<<(NN + 1 + 255) / 256, 256>>>(dst, rowptr);

    const int my = (NN + TBM - 1) / TBM;                 // 782
    const int node_grid = (NN + 7) / 8;                  // warp/node (8 warps/block)
    const int nodehead_grid = (NN * HH + 7) / 8;

    // ---- layer 0: x[100k,100] -> 128, Linear residual (3 outputs, 1 launch) ----
    gemm_tc3<<<dim3(3, my), 256>>>(x, Wsrc0, Wdst0, Wres0, bsrc0, bdst0, bres0,
                                   fs, fd, res, NN, IND, HD, 1, nullptr, nullptr);
    gat_fused128<false><<<node_grid, 256>>>((const float4*)fs, (const float4*)fd,
                                            (const float4*)attn0, src, rowptr,
                                            (const float4*)res, nullptr, nullptr,
                                            (float4*)tmp);
    bn_stats<<<2048, 128>>>(tmp);
    bn_finalize<<<1, 128>>>(g0, be0, sc0, sh0);

    // ---- layer 1: A = relu(bn0(tmp)), Identity residual = same ----
    gemm_tc3<<<dim3(2, my), 256>>>(tmp, Wsrc1, Wdst1, Wdst1, bsrc1, bdst1, bdst1,
                                   fs, fd, fd, NN, HD, HD, 1, sc0, sh0);
    gat_fused128<true><<<node_grid, 256>>>((const float4*)fs, (const float4*)fd,
                                           (const float4*)attn1, src, rowptr,
                                           (const float4*)tmp, (const float4*)sc0,
                                           (const float4*)sh0, (float4*)tmp2);
    bn_stats<<<2048, 128>>>(tmp2);
    bn_finalize<<<1, 128>>>(g1, be1, sc1, sh1);

    // ---- layer 2: A = relu(bn1(tmp2)) -> 188, Linear residual, no BN ----
    gemm_tc3<<<dim3(6, my), 256>>>(tmp2, Wsrc2, Wdst2, Wres2, bsrc2, bdst2, bres2,
                                   fs, fd, res, NN, HD, HC, 2, sc1, sh1);
    gat_fusedN<CC><<<nodehead_grid, 256>>>(fs, fd, attn2, src, rowptr, res, tmp);

    final_logsoftmax<<<(NN + 7) / 8, 256>>>(tmp, out);
}

// round 10
// speedup vs baseline: 3.1939x; 1.0106x over previous
#include <cuda_runtime.h>
#include <math.h>
#include <stdint.h>

#define NN 100000
#define EE 1000000
#define IND 100
#define HH 4
#define DD 32
#define CC 47
#define HD 128
#define HC 188
#define EPSI 1e-5f
#define SLP 0.2f

// ---------------- scratch (static device memory; no allocation) ----------------
__device__ float g_fs[(size_t)NN * HC];
__device__ float g_fd[(size_t)NN * HC];
__device__ float g_res[(size_t)NN * HC];
__device__ float g_tmp[(size_t)NN * HC];
__device__ float g_tmp2[(size_t)NN * HD];
__device__ int   g_rowptr[NN + 1];
__device__ float g_stats[2 * HD];
__device__ float g_sc0[HD], g_sh0[HD], g_sc1[HD], g_sh1[HD];

// ---------------- CSR row_ptr from sorted dst (also zeroes BN stats) ----------------
__global__ void rowptr_kernel(const int* __restrict__ dst, int* __restrict__ rowptr) {
    int n = blockIdx.x * blockDim.x + threadIdx.x;
    if (blockIdx.x == 0 && threadIdx.x < 2 * HD) g_stats[threadIdx.x] = 0.f;
    if (n > NN) return;
    int lo = 0, hi = EE;
    while (lo < hi) {
        int mid = (lo + hi) >> 1;
        if (dst[mid] < n) lo = mid + 1; else hi = mid;
    }
    rowptr[n] = lo;
}

// ---------------- tf32 helpers ----------------
__device__ __forceinline__ uint32_t f2tf(float f) {
    uint32_t r;
    asm("cvt.rna.tf32.f32 %0, %1;" : "=r"(r) : "f"(f));
    return r;
}

__device__ __forceinline__ void mma_tf32(float* c, const uint32_t* a, const uint32_t* b) {
    asm volatile(
        "mma.sync.aligned.m16n8k8.row.col.f32.tf32.tf32.f32 "
        "{%0,%1,%2,%3}, {%4,%5,%6,%7}, {%8,%9}, {%0,%1,%2,%3};"
        : "+f"(c[0]), "+f"(c[1]), "+f"(c[2]), "+f"(c[3])
        : "r"(a[0]), "r"(a[1]), "r"(a[2]), "r"(a[3]), "r"(b[0]), "r"(b[1]));
}

// ---------------- tf32 tensor-core GEMM: 128x128 tile, BK=32, 8 warps ----------------
#define TBM 128
#define TBN 128
#define TBK 32
#define ASTRIDE 36
#define BSTRIDE 136

__device__ __forceinline__ float4 ldA_aff(const float4* __restrict__ A4, int gm, int gk,
                                          int M, int K, int K4,
                                          const float* __restrict__ bnsc,
                                          const float* __restrict__ bnsh) {
    float4 a = make_float4(0.f, 0.f, 0.f, 0.f);
    if (gm < M && gk < K) {
        a = A4[(size_t)gm * K4 + (gk >> 2)];
        if (bnsc) {
            float4 s = *(const float4*)&bnsc[gk];
            float4 t = *(const float4*)&bnsh[gk];
            a.x = fmaxf(fmaf(a.x, s.x, t.x), 0.f);
            a.y = fmaxf(fmaf(a.y, s.y, t.y), 0.f);
            a.z = fmaxf(fmaf(a.z, s.z, t.z), 0.f);
            a.w = fmaxf(fmaf(a.w, s.w, t.w), 0.f);
        }
    }
    return a;
}

__global__ __launch_bounds__(256) void gemm_tc3(
    const float* __restrict__ A,
    const float* __restrict__ W0, const float* __restrict__ W1, const float* __restrict__ W2,
    const float* __restrict__ b0p, const float* __restrict__ b1p, const float* __restrict__ b2p,
    float* __restrict__ C0, float* __restrict__ C1, float* __restrict__ C2,
    int M, int K, int Nc, int tilesPer,
    const float* __restrict__ bnsc, const float* __restrict__ bnsh) {
    __shared__ uint32_t As[TBM][ASTRIDE];
    __shared__ uint32_t Bs[TBK][BSTRIDE];

    int which = blockIdx.x / tilesPer;
    int xt = blockIdx.x - which * tilesPer;
    const float* W = which == 0 ? W0 : (which == 1 ? W1 : W2);
    const float* bias = which == 0 ? b0p : (which == 1 ? b1p : b2p);
    float* C = which == 0 ? C0 : (which == 1 ? C1 : C2);

    int bm = blockIdx.y * TBM, bn = xt * TBN;
    int tid = threadIdx.x;
    int wid = tid >> 5, lane = tid & 31;
    int warpM = wid & 1, warpN = wid >> 1;
    int g = lane >> 2, tig = lane & 3;

    float acc[4][4][4];
#pragma unroll
    for (int mi = 0; mi < 4; mi++)
#pragma unroll
        for (int ni = 0; ni < 4; ni++)
#pragma unroll
            for (int r = 0; r < 4; r++) acc[mi][ni][r] = 0.f;

    const float4* A4 = (const float4*)A;
    const float4* W4 = (const float4*)W;
    int K4 = K >> 2, Nc4 = Nc >> 2;
    int T = (K + TBK - 1) / TBK;

    float4 rA[4], rB[4];

#pragma unroll
    for (int i = 0; i < 4; i++) {
        int idx = tid + i * 256;
        int m = idx >> 3, kq = idx & 7;
        rA[i] = ldA_aff(A4, bm + m, kq * 4, M, K, K4, bnsc, bnsh);
    }
#pragma unroll
    for (int i = 0; i < 4; i++) {
        int idx = tid + i * 256;
        int k = idx >> 5, nq = idx & 31;
        int gn = bn + nq * 4;
        rB[i] = make_float4(0.f, 0.f, 0.f, 0.f);
        if (k < K && gn < Nc) rB[i] = W4[(size_t)k * Nc4 + (gn >> 2)];
    }

    for (int t = 0; t < T; t++) {
#pragma unroll
        for (int i = 0; i < 4; i++) {
            int idx = tid + i * 256;
            int m = idx >> 3, kq = idx & 7;
            As[m][kq * 4 + 0] = f2tf(rA[i].x);
            As[m][kq * 4 + 1] = f2tf(rA[i].y);
            As[m][kq * 4 + 2] = f2tf(rA[i].z);
            As[m][kq * 4 + 3] = f2tf(rA[i].w);
        }
#pragma unroll
        for (int i = 0; i < 4; i++) {
            int idx = tid + i * 256;
            int k = idx >> 5, nq = idx & 31;
            Bs[k][nq * 4 + 0] = f2tf(rB[i].x);
            Bs[k][nq * 4 + 1] = f2tf(rB[i].y);
            Bs[k][nq * 4 + 2] = f2tf(rB[i].z);
            Bs[k][nq * 4 + 3] = f2tf(rB[i].w);
        }
        __syncthreads();

        if (t + 1 < T) {
            int k0 = (t + 1) * TBK;
#pragma unroll
            for (int i = 0; i < 4; i++) {
                int idx = tid + i * 256;
                int m = idx >> 3, kq = idx & 7;
                rA[i] = ldA_aff(A4, bm + m, k0 + kq * 4, M, K, K4, bnsc, bnsh);
            }
#pragma unroll
            for (int i = 0; i < 4; i++) {
                int idx = tid + i * 256;
                int k = idx >> 5, nq = idx & 31;
                int gk = k0 + k, gn = bn + nq * 4;
                rB[i] = make_float4(0.f, 0.f, 0.f, 0.f);
                if (gk < K && gn < Nc) rB[i] = W4[(size_t)gk * Nc4 + (gn >> 2)];
            }
        }

#pragma unroll
        for (int ks = 0; ks < 4; ks++) {
            int Ck = ks * 8;
            uint32_t af[4][4];
#pragma unroll
            for (int mi = 0; mi < 4; mi++) {
                int r = warpM * 64 + mi * 16;
                af[mi][0] = As[r + g][Ck + tig];
                af[mi][1] = As[r + g + 8][Ck + tig];
                af[mi][2] = As[r + g][Ck + tig + 4];
                af[mi][3] = As[r + g + 8][Ck + tig + 4];
            }
            uint32_t bf[4][2];
#pragma unroll
            for (int ni = 0; ni < 4; ni++) {
                int c = warpN * 32 + ni * 8;
                bf[ni][0] = Bs[Ck + tig][c + g];
                bf[ni][1] = Bs[Ck + tig + 4][c + g];
            }
#pragma unroll
            for (int mi = 0; mi < 4; mi++)
#pragma unroll
                for (int ni = 0; ni < 4; ni++)
                    mma_tf32(acc[mi][ni], af[mi], bf[ni]);
        }
        __syncthreads();
    }

#pragma unroll
    for (int ni = 0; ni < 4; ni++) {
        int gn = bn + warpN * 32 + ni * 8 + 2 * tig;
        if (gn + 1 >= Nc && gn >= Nc) continue;
        float2 bb = *(const float2*)&bias[gn];
#pragma unroll
        for (int mi = 0; mi < 4; mi++) {
            int gm = bm + warpM * 64 + mi * 16 + g;
            if (gm < M) {
                float2 o = make_float2(acc[mi][ni][0] + bb.x, acc[mi][ni][1] + bb.y);
                *(float2*)&C[(size_t)gm * Nc + gn] = o;
            }
            if (gm + 8 < M) {
                float2 o = make_float2(acc[mi][ni][2] + bb.x, acc[mi][ni][3] + bb.y);
                *(float2*)&C[(size_t)(gm + 8) * Nc + gn] = o;
            }
        }
    }
}

// ---------------- fused GATv2, LD=128: warp/node, 4-edge unroll, optional fused BN stats ----
__device__ __forceinline__ float dot_leaky(const float4 f, const float4 fdl, const float4 al) {
    float vx = f.x + fdl.x; vx = vx > 0.f ? vx : SLP * vx;
    float vy = f.y + fdl.y; vy = vy > 0.f ? vy : SLP * vy;
    float vz = f.z + fdl.z; vz = vz > 0.f ? vz : SLP * vz;
    float vw = f.w + fdl.w; vw = vw > 0.f ? vw : SLP * vw;
    return vx * al.x + vy * al.y + vz * al.z + vw * al.w;
}

template <bool BNRES, bool STATS>
__global__ void gat_fused128(const float4* __restrict__ fs, const float4* __restrict__ fd,
                             const float4* __restrict__ attn,
                             const int* __restrict__ src, const int* __restrict__ rowptr,
                             const float4* __restrict__ res,
                             const float4* __restrict__ bnsc, const float4* __restrict__ bnsh,
                             float4* __restrict__ out) {
    __shared__ float s_red[8][HD];
    int tid = threadIdx.x;
    int n = blockIdx.x * 8 + (tid >> 5);
    int wid = tid >> 5;
    int q = tid & 31;
    bool active = n < NN;

    float4 fdl = make_float4(0.f, 0.f, 0.f, 0.f), al = fdl;
    int e0 = 0, e1 = 0;
    if (active) {
        fdl = fd[(size_t)n * 32 + q];
        al = attn[q];
        e0 = rowptr[n]; e1 = rowptr[n + 1];
    }

    float m = -INFINITY, ssum = 0.f;
    float ax = 0.f, ay = 0.f, az = 0.f, aw = 0.f;
    int e = e0;
    for (; e + 3 < e1; e += 4) {
        int s0 = src[e], s1 = src[e + 1], s2 = src[e + 2], s3 = src[e + 3];
        float4 f0 = fs[(size_t)s0 * 32 + q];
        float4 f1 = fs[(size_t)s1 * 32 + q];
        float4 f2 = fs[(size_t)s2 * 32 + q];
        float4 f3 = fs[(size_t)s3 * 32 + q];
        float l0 = dot_leaky(f0, fdl, al);
        float l1 = dot_leaky(f1, fdl, al);
        float l2 = dot_leaky(f2, fdl, al);
        float l3 = dot_leaky(f3, fdl, al);
#pragma unroll
        for (int o = 4; o; o >>= 1) {
            l0 += __shfl_xor_sync(0xffffffffu, l0, o);
            l1 += __shfl_xor_sync(0xffffffffu, l1, o);
            l2 += __shfl_xor_sync(0xffffffffu, l2, o);
            l3 += __shfl_xor_sync(0xffffffffu, l3, o);
        }
        float nm = fmaxf(m, fmaxf(fmaxf(l0, l1), fmaxf(l2, l3)));
        float sc = __expf(m - nm);
        float w0 = __expf(l0 - nm);
        float w1 = __expf(l1 - nm);
        float w2 = __expf(l2 - nm);
        float w3 = __expf(l3 - nm);
        ssum = ssum * sc + ((w0 + w1) + (w2 + w3));
        ax = ax * sc + (w0 * f0.x + w1 * f1.x) + (w2 * f2.x + w3 * f3.x);
        ay = ay * sc + (w0 * f0.y + w1 * f1.y) + (w2 * f2.y + w3 * f3.y);
        az = az * sc + (w0 * f0.z + w1 * f1.z) + (w2 * f2.z + w3 * f3.z);
        aw = aw * sc + (w0 * f0.w + w1 * f1.w) + (w2 * f2.w + w3 * f3.w);
        m = nm;
    }
    for (; e < e1; e++) {
        int s0 = src[e];
        float4 f0 = fs[(size_t)s0 * 32 + q];
        float l0 = dot_leaky(f0, fdl, al);
#pragma unroll
        for (int o = 4; o; o >>= 1) l0 += __shfl_xor_sync(0xffffffffu, l0, o);
        float nm = fmaxf(m, l0);
        float sc = __expf(m - nm);
        float w0 = __expf(l0 - nm);
        ssum = ssum * sc + w0;
        ax = ax * sc + w0 * f0.x;
        ay = ay * sc + w0 * f0.y;
        az = az * sc + w0 * f0.z;
        aw = aw * sc + w0 * f0.w;
        m = nm;
    }

    float4 o = make_float4(0.f, 0.f, 0.f, 0.f);
    if (active) {
        float inv = (e1 > e0) ? 1.f / ssum : 0.f;
        float4 r = res[(size_t)n * 32 + q];
        if (BNRES) {
            float4 s = bnsc[q], t = bnsh[q];
            r.x = fmaxf(fmaf(r.x, s.x, t.x), 0.f);
            r.y = fmaxf(fmaf(r.y, s.y, t.y), 0.f);
            r.z = fmaxf(fmaf(r.z, s.z, t.z), 0.f);
            r.w = fmaxf(fmaf(r.w, s.w, t.w), 0.f);
        }
        o.x = fmaxf(ax * inv + r.x, 0.f);
        o.y = fmaxf(ay * inv + r.y, 0.f);
        o.z = fmaxf(az * inv + r.z, 0.f);
        o.w = fmaxf(aw * inv + r.w, 0.f);
        out[(size_t)n * 32 + q] = o;
    }

    if (STATS) {
        *(float4*)&s_red[wid][q * 4] = o;   // zeros if inactive
        __syncthreads();
        if (tid < HD) {
            float s = 0.f, qq = 0.f;
#pragma unroll
            for (int w = 0; w < 8; w++) {
                float v = s_red[w][tid];
                s += v; qq += v * v;
            }
            atomicAdd(&g_stats[tid], s);
            atomicAdd(&g_stats[HD + tid], qq);
        }
    }
}

// ---------------- fused GATv2, generic (layer 2, DH=47, no relu), 4-edge unroll ----------------
template <int DH>
__global__ void gat_fusedN(const float* __restrict__ fs, const float* __restrict__ fd,
                           const float* __restrict__ attn,
                           const int* __restrict__ src, const int* __restrict__ rowptr,
                           const float* __restrict__ res, float* __restrict__ out) {
    const int LD = HH * DH;
    int gw = blockIdx.x * (blockDim.x >> 5) + (threadIdx.x >> 5);
    if (gw >= NN * HH) return;
    int n = gw >> 2, h = gw & 3;
    int lane = threadIdx.x & 31;
    int d0 = lane, d1 = lane + 32;
    const bool b1 = d1 < DH;

    size_t nb = (size_t)n * LD + h * DH;
    float fd0 = fd[nb + d0];
    float a0 = attn[h * DH + d0];
    float fd1 = b1 ? fd[nb + d1] : 0.f;
    float a1 = b1 ? attn[h * DH + d1] : 0.f;

    int e0 = rowptr[n], e1 = rowptr[n + 1];
    float m = -INFINITY, ssum = 0.f, acc0 = 0.f, acc1 = 0.f;
    int e = e0;
    for (; e + 3 < e1; e += 4) {
        float fA[4], fB[4], lg[4];
#pragma unroll
        for (int j = 0; j < 4; j++) {
            int s = src[e + j];
            const float* rr = fs + (size_t)s * LD + h * DH;
            fA[j] = rr[d0];
            fB[j] = b1 ? rr[d1] : 0.f;
        }
#pragma unroll
        for (int j = 0; j < 4; j++) {
            float u = fA[j] + fd0; u = u > 0.f ? u : SLP * u;
            float w = fB[j] + fd1; w = w > 0.f ? w : SLP * w;
            lg[j] = u * a0 + w * a1;
        }
#pragma unroll
        for (int o = 16; o; o >>= 1) {
            lg[0] += __shfl_xor_sync(0xffffffffu, lg[0], o);
            lg[1] += __shfl_xor_sync(0xffffffffu, lg[1], o);
            lg[2] += __shfl_xor_sync(0xffffffffu, lg[2], o);
            lg[3] += __shfl_xor_sync(0xffffffffu, lg[3], o);
        }
        float nm = fmaxf(m, fmaxf(fmaxf(lg[0], lg[1]), fmaxf(lg[2], lg[3])));
        float sc = __expf(m - nm);
        float w0 = __expf(lg[0] - nm);
        float w1 = __expf(lg[1] - nm);
        float w2 = __expf(lg[2] - nm);
        float w3 = __expf(lg[3] - nm);
        ssum = ssum * sc + ((w0 + w1) + (w2 + w3));
        acc0 = acc0 * sc + (w0 * fA[0] + w1 * fA[1]) + (w2 * fA[2] + w3 * fA[3]);
        acc1 = acc1 * sc + (w0 * fB[0] + w1 * fB[1]) + (w2 * fB[2] + w3 * fB[3]);
        m = nm;
    }
    for (; e < e1; e++) {
        int s0 = src[e];
        const float* r0 = fs + (size_t)s0 * LD + h * DH;
        float f00 = r0[d0];
        float f01 = b1 ? r0[d1] : 0.f;
        float u0 = f00 + fd0; u0 = u0 > 0.f ? u0 : SLP * u0;
        float w0 = f01 + fd1; w0 = w0 > 0.f ? w0 : SLP * w0;
        float l0 = u0 * a0 + w0 * a1;
#pragma unroll
        for (int o = 16; o; o >>= 1) l0 += __shfl_xor_sync(0xffffffffu, l0, o);
        float nm = fmaxf(m, l0);
        float sc = __expf(m - nm);
        float w0e = __expf(l0 - nm);
        ssum = ssum * sc + w0e;
        acc0 = acc0 * sc + w0e * f00;
        acc1 = acc1 * sc + w0e * f01;
        m = nm;
    }
    float inv = (e1 > e0) ? 1.f / ssum : 0.f;
    out[nb + d0] = acc0 * inv + res[nb + d0];
    if (b1) out[nb + d1] = acc1 * inv + res[nb + d1];
}

// ---------------- BN finalize (stats accumulated inside gat_fused128) ----------------
__global__ void bn_finalize(const float* __restrict__ g, const float* __restrict__ b,
                            float* __restrict__ sc, float* __restrict__ sh) {
    int c = threadIdx.x;  // 128
    float mu = g_stats[c] * (1.f / NN);
    float var = g_stats[HD + c] * (1.f / NN) - mu * mu;
    float s = g[c] * rsqrtf(var + EPSI);
    sc[c] = s;
    sh[c] = b[c] - mu * s;
    g_stats[c] = 0.f;
    g_stats[HD + c] = 0.f;
}

// ---------------- head mean + log_softmax (warp per node) ----------------
__global__ void final_logsoftmax(const float* __restrict__ h, float* __restrict__ out) {
    int n = blockIdx.x * (blockDim.x >> 5) + (threadIdx.x >> 5);
    int lane = threadIdx.x & 31;
    if (n >= NN) return;
    const float* row = h + (size_t)n * HC;
    int c0 = lane, c1 = lane + 32;
    bool a0 = c0 < CC, a1 = c1 < CC;
    float v0 = 0.f, v1 = 0.f;
    if (a0) v0 = 0.25f * (row[c0] + row[CC + c0] + row[2 * CC + c0] + row[3 * CC + c0]);
    if (a1) v1 = 0.25f * (row[c1] + row[CC + c1] + row[2 * CC + c1] + row[3 * CC + c1]);
    float mx = fmaxf(a0 ? v0 : -INFINITY, a1 ? v1 : -INFINITY);
#pragma unroll
    for (int o = 16; o; o >>= 1) mx = fmaxf(mx, __shfl_xor_sync(0xffffffffu, mx, o));
    float s = (a0 ? __expf(v0 - mx) : 0.f) + (a1 ? __expf(v1 - mx) : 0.f);
#pragma unroll
    for (int o = 16; o; o >>= 1) s += __shfl_xor_sync(0xffffffffu, s, o);
    float ls = logf(s);
    if (a0) out[(size_t)n * CC + c0] = v0 - mx - ls;
    if (a1) out[(size_t)n * CC + c1] = v1 - mx - ls;
}

extern "C" void kernel_launch(void* const* d_in, const int* in_sizes, int n_in,
                              void* d_out, int out_size) {
    const float* x     = (const float*)d_in[0];
    const int*   src   = (const int*)d_in[1];
    const int*   dst   = (const int*)d_in[2];
    const float* Wsrc0 = (const float*)d_in[3];
    const float* bsrc0 = (const float*)d_in[4];
    const float* Wdst0 = (const float*)d_in[5];
    const float* bdst0 = (const float*)d_in[6];
    const float* attn0 = (const float*)d_in[7];
    const float* Wres0 = (const float*)d_in[8];
    const float* bres0 = (const float*)d_in[9];
    const float* Wsrc1 = (const float*)d_in[10];
    const float* bsrc1 = (const float*)d_in[11];
    const float* Wdst1 = (const float*)d_in[12];
    const float* bdst1 = (const float*)d_in[13];
    const float* attn1 = (const float*)d_in[14];
    const float* Wsrc2 = (const float*)d_in[15];
    const float* bsrc2 = (const float*)d_in[16];
    const float* Wdst2 = (const float*)d_in[17];
    const float* bdst2 = (const float*)d_in[18];
    const float* attn2 = (const float*)d_in[19];
    const float* Wres2 = (const float*)d_in[20];
    const float* bres2 = (const float*)d_in[21];
    const float* g0    = (const float*)d_in[22];
    const float* be0   = (const float*)d_in[23];
    const float* g1    = (const float*)d_in[24];
    const float* be1   = (const float*)d_in[25];
    float* out = (float*)d_out;

    float *fs, *fd, *res, *tmp, *tmp2, *sc0, *sh0, *sc1, *sh1;
    int* rowptr;
    cudaGetSymbolAddress((void**)&fs, g_fs);
    cudaGetSymbolAddress((void**)&fd, g_fd);
    cudaGetSymbolAddress((void**)&res, g_res);
    cudaGetSymbolAddress((void**)&tmp, g_tmp);
    cudaGetSymbolAddress((void**)&tmp2, g_tmp2);
    cudaGetSymbolAddress((void**)&rowptr, g_rowptr);
    cudaGetSymbolAddress((void**)&sc0, g_sc0);
    cudaGetSymbolAddress((void**)&sh0, g_sh0);
    cudaGetSymbolAddress((void**)&sc1, g_sc1);
    cudaGetSymbolAddress((void**)&sh1, g_sh1);

    rowptr_kernel<<<(NN + 1 + 255) / 256, 256>>>(dst, rowptr);

    const int my = (NN + TBM - 1) / TBM;                 // 782
    const int node_grid = (NN + 7) / 8;                  // warp/node (8 warps/block)
    const int nodehead_grid = (NN * HH + 7) / 8;

    // ---- layer 0: x[100k,100] -> 128, Linear residual (3 outputs, 1 launch) ----
    gemm_tc3<<<dim3(3, my), 256>>>(x, Wsrc0, Wdst0, Wres0, bsrc0, bdst0, bres0,
                                   fs, fd, res, NN, IND, HD, 1, nullptr, nullptr);
    gat_fused128<false, true><<<node_grid, 256>>>((const float4*)fs, (const float4*)fd,
                                                  (const float4*)attn0, src, rowptr,
                                                  (const float4*)res, nullptr, nullptr,
                                                  (float4*)tmp);
    bn_finalize<<<1, 128>>>(g0, be0, sc0, sh0);

    // ---- layer 1: A = relu(bn0(tmp)), Identity residual = same ----
    gemm_tc3<<<dim3(2, my), 256>>>(tmp, Wsrc1, Wdst1, Wdst1, bsrc1, bdst1, bdst1,
                                   fs, fd, fd, NN, HD, HD, 1, sc0, sh0);
    gat_fused128<true, true><<<node_grid, 256>>>((const float4*)fs, (const float4*)fd,
                                                 (const float4*)attn1, src, rowptr,
                                                 (const float4*)tmp, (const float4*)sc0,
                                                 (const float4*)sh0, (float4*)tmp2);
    bn_finalize<<<1, 128>>>(g1, be1, sc1, sh1);

    // ---- layer 2: A = relu(bn1(tmp2)) -> 188, Linear residual, no BN ----
    gemm_tc3<<<dim3(6, my), 256>>>(tmp2, Wsrc2, Wdst2, Wres2, bsrc2, bdst2, bres2,
                                   fs, fd, res, NN, HD, HC, 2, sc1, sh1);
    gat_fusedN<CC><<<nodehead_grid, 256>>>(fs, fd, attn2, src, rowptr, res, tmp);

    final_logsoftmax<<<(NN + 7) / 8, 256>>>(tmp, out);
}